// round 2
// baseline (speedup 1.0000x reference)
#include <cuda_runtime.h>
#include <cstddef>

// ---------------- problem constants ----------------
#define N0v   320000
#define N1v   80000
#define N2v   16000
#define E1v   800000
#define E2v   160000
#define INCv  128
#define HIDv  64
#define H1c   4
#define OUTCv 48
#define D1v   (H1c*HIDv)   // 256

// ---------------- scratch (device globals; no allocations allowed) ----------------
__device__ float g_xl1[(size_t)N0v * D1v];   // x @ Wl1 + bl1          (327 MB)
__device__ float g_xr1[(size_t)N1v * D1v];   // x[:N1] @ Wr1 + br1     (82 MB)
__device__ float g_h  [(size_t)N1v * D1v];   // layer-1 output (relu)  (82 MB)
__device__ float g_xl2[(size_t)N1v * OUTCv]; // h @ Wl2 + bl2
__device__ float g_xr2[(size_t)N2v * OUTCv]; // h[:N2] @ Wr2 + br2

__device__ int g_cnt1[N1v], g_off1[N1v], g_cur1[N1v];
__device__ int g_cnt2[N2v], g_off2[N2v], g_cur2[N2v];
__device__ int g_eidx1[E1v], g_eidx2[E2v];
__device__ int g_part1[256], g_part2[256];

// ---------------- packed f32x2 helpers (2x fp32 FMA rate on sm_103a) ----------------
__device__ __forceinline__ unsigned long long pack2(float lo, float hi) {
    unsigned long long r;
    asm("mov.b64 %0, {%1,%2};" : "=l"(r) : "f"(lo), "f"(hi));
    return r;
}
__device__ __forceinline__ void unpack2(unsigned long long v, float& lo, float& hi) {
    asm("mov.b64 {%0,%1}, %2;" : "=f"(lo), "=f"(hi) : "l"(v));
}
__device__ __forceinline__ unsigned long long fma2(unsigned long long a,
                                                   unsigned long long b,
                                                   unsigned long long c) {
    unsigned long long r;
    asm("fma.rn.f32x2 %0, %1, %2, %3;" : "=l"(r) : "l"(a), "l"(b), "l"(c));
    return r;
}

// ---------------- GEMM: C[M,N] = A[M,K] @ B[K,N] + bias[N] ----------------
// BM=128, BN=128, BK=16, 256 threads, 8x8 micro-tile with f32x2 accumulators.
__global__ __launch_bounds__(256) void gemm_bias(const float* __restrict__ A,
                                                 const float* __restrict__ B,
                                                 const float* __restrict__ bias,
                                                 float* __restrict__ C,
                                                 int M, int N, int K) {
    __shared__ float As[16][128];   // [k][m]
    __shared__ float Bs[16][128];   // [k][n]
    const int t  = threadIdx.x;
    const int tx = t & 15;          // column group
    const int ty = t >> 4;          // row group
    const int m0 = blockIdx.y * 128;
    const int n0 = blockIdx.x * 128;

    unsigned long long acc[8][4];
#pragma unroll
    for (int i = 0; i < 8; i++)
#pragma unroll
        for (int j = 0; j < 4; j++) acc[i][j] = 0ull;

    for (int k0 = 0; k0 < K; k0 += 16) {
        // A tile: 128 rows x 16 k (transposed into As[k][m])
#pragma unroll
        for (int i = 0; i < 2; i++) {
            int idx = t + i * 256;          // 0..511
            int row = idx >> 2;             // 0..127
            int col = (idx & 3) << 2;       // 0,4,8,12
            float4 v = make_float4(0.f, 0.f, 0.f, 0.f);
            int gr = m0 + row;
            if (gr < M)
                v = *reinterpret_cast<const float4*>(&A[(size_t)gr * K + k0 + col]);
            As[col + 0][row] = v.x; As[col + 1][row] = v.y;
            As[col + 2][row] = v.z; As[col + 3][row] = v.w;
        }
        // B tile: 16 k x 128 n
#pragma unroll
        for (int i = 0; i < 2; i++) {
            int idx = t + i * 256;
            int row = idx >> 5;             // 0..15
            int col = (idx & 31) << 2;      // 0..124
            int gc  = n0 + col;
            float4 v = make_float4(0.f, 0.f, 0.f, 0.f);
            const float* brow = &B[(size_t)(k0 + row) * N];
            if (gc + 3 < N) {
                v = *reinterpret_cast<const float4*>(&brow[gc]);
            } else {
                if (gc + 0 < N) v.x = brow[gc + 0];
                if (gc + 1 < N) v.y = brow[gc + 1];
                if (gc + 2 < N) v.z = brow[gc + 2];
            }
            *reinterpret_cast<float4*>(&Bs[row][col]) = v;
        }
        __syncthreads();
#pragma unroll
        for (int k = 0; k < 16; k++) {
            float4 a0 = *reinterpret_cast<const float4*>(&As[k][ty * 8]);
            float4 a1 = *reinterpret_cast<const float4*>(&As[k][ty * 8 + 4]);
            ulonglong2 b0 = *reinterpret_cast<const ulonglong2*>(&Bs[k][tx * 8]);
            ulonglong2 b1 = *reinterpret_cast<const ulonglong2*>(&Bs[k][tx * 8 + 4]);
            float ar[8] = {a0.x, a0.y, a0.z, a0.w, a1.x, a1.y, a1.z, a1.w};
            unsigned long long bb[4] = {b0.x, b0.y, b1.x, b1.y};
#pragma unroll
            for (int i = 0; i < 8; i++) {
                unsigned long long a2 = pack2(ar[i], ar[i]);
#pragma unroll
                for (int j = 0; j < 4; j++) acc[i][j] = fma2(a2, bb[j], acc[i][j]);
            }
        }
        __syncthreads();
    }
#pragma unroll
    for (int i = 0; i < 8; i++) {
        int gr = m0 + ty * 8 + i;
        if (gr >= M) continue;
#pragma unroll
        for (int j = 0; j < 4; j++) {
            float lo, hi;
            unpack2(acc[i][j], lo, hi);
            int gc = n0 + tx * 8 + j * 2;
            if (gc < N)     C[(size_t)gr * N + gc]     = lo + bias[gc];
            if (gc + 1 < N) C[(size_t)gr * N + gc + 1] = hi + bias[gc + 1];
        }
    }
}

// ---------------- CSR build helpers ----------------
__global__ void k_zero(int* p, int n) {
    int i = blockIdx.x * blockDim.x + threadIdx.x;
    if (i < n) p[i] = 0;
}
__global__ void k_count(const int* __restrict__ dst, int* __restrict__ cnt, int E) {
    int e = blockIdx.x * blockDim.x + threadIdx.x;
    if (e < E) atomicAdd(&cnt[dst[e]], 1);
}
__global__ __launch_bounds__(1024) void k_scan_block(const int* __restrict__ in,
                                                     int* __restrict__ out,
                                                     int* __restrict__ part, int n) {
    __shared__ int sh[1024];
    int t = threadIdx.x;
    int i = blockIdx.x * 1024 + t;
    int v = (i < n) ? in[i] : 0;
    sh[t] = v;
    __syncthreads();
    for (int d = 1; d < 1024; d <<= 1) {
        int add = (t >= d) ? sh[t - d] : 0;
        __syncthreads();
        sh[t] += add;
        __syncthreads();
    }
    if (i < n) out[i] = sh[t] - v;               // exclusive
    if (t == 1023) part[blockIdx.x] = sh[1023];  // block total
}
__global__ __launch_bounds__(1024) void k_scan_part(int* part, int nb) {
    __shared__ int sh[1024];
    int t = threadIdx.x;
    int v = (t < nb) ? part[t] : 0;
    sh[t] = v;
    __syncthreads();
    for (int d = 1; d < 1024; d <<= 1) {
        int add = (t >= d) ? sh[t - d] : 0;
        __syncthreads();
        sh[t] += add;
        __syncthreads();
    }
    if (t < nb) part[t] = sh[t] - v;             // exclusive
}
__global__ __launch_bounds__(1024) void k_scan_add(int* out, const int* part, int n) {
    int i = blockIdx.x * 1024 + threadIdx.x;
    if (i < n) out[i] += part[blockIdx.x];
}
__global__ void k_scatter(const int* __restrict__ dst, const int* __restrict__ off,
                          int* __restrict__ cur, int* __restrict__ eidx, int E) {
    int e = blockIdx.x * blockDim.x + threadIdx.x;
    if (e < E) {
        int d = dst[e];
        int p = off[d] + atomicAdd(&cur[d], 1);
        eidx[p] = e;
    }
}
// deterministic per-bucket order (insertion sort; avg bucket ~10)
__global__ void k_sort(const int* __restrict__ off, const int* __restrict__ cnt,
                       int* __restrict__ eidx, int n) {
    int i = blockIdx.x * blockDim.x + threadIdx.x;
    if (i >= n) return;
    int a = off[i], c = cnt[i];
    for (int x = 1; x < c; x++) {
        int key = eidx[a + x];
        int y = x - 1;
        while (y >= 0 && eidx[a + y] > key) { eidx[a + y + 1] = eidx[a + y]; y--; }
        eidx[a + y + 1] = key;
    }
}

// ---------------- layer-1 aggregation: warp per dst node, online softmax ----------------
// channels: ch = lane + 32*k, k=0..7; head = k>>1; att flat index == ch.
__global__ __launch_bounds__(256) void k_agg1(const int* __restrict__ src,
                                              const int* __restrict__ eidx,
                                              const int* __restrict__ off,
                                              const int* __restrict__ cnt,
                                              const float* __restrict__ att,
                                              const float* __restrict__ bias) {
    int warp = (blockIdx.x * blockDim.x + threadIdx.x) >> 5;
    int lane = threadIdx.x & 31;
    if (warp >= N1v) return;

    const float* xr = &g_xr1[(size_t)warp * D1v];
    float xrr[8], attr[8], s[8], m[4], d[4];
#pragma unroll
    for (int k = 0; k < 8; k++) {
        int ch = lane + 32 * k;
        xrr[k] = xr[ch];
        attr[k] = att[ch];
        s[k] = 0.f;
    }
#pragma unroll
    for (int h = 0; h < 4; h++) { m[h] = -1e30f; d[h] = 0.f; }

    int a0 = off[warp], c = cnt[warp];
    for (int j = 0; j < c; j++) {
        int e  = eidx[a0 + j];
        int sn = src[e];
        const float* xlp = &g_xl1[(size_t)sn * D1v];
        float xl[8];
#pragma unroll
        for (int k = 0; k < 8; k++) xl[k] = xlp[lane + 32 * k];
#pragma unroll
        for (int h = 0; h < 4; h++) {
            float p = 0.f;
#pragma unroll
            for (int kk = 0; kk < 2; kk++) {
                int k = 2 * h + kk;
                float ev = xl[k] + xrr[k];
                ev = ev > 0.f ? ev : 0.2f * ev;   // leaky_relu
                p += ev * attr[k];
            }
#pragma unroll
            for (int o = 16; o; o >>= 1) p += __shfl_xor_sync(0xffffffffu, p, o);
            float mn = fmaxf(m[h], p);
            float c1 = __expf(m[h] - mn);
            float c2 = __expf(p - mn);
            d[h] = d[h] * c1 + c2;
            m[h] = mn;
#pragma unroll
            for (int kk = 0; kk < 2; kk++) {
                int k = 2 * h + kk;
                s[k] = s[k] * c1 + c2 * xl[k];
            }
        }
    }
    float* hp = &g_h[(size_t)warp * D1v];
#pragma unroll
    for (int k = 0; k < 8; k++) {
        int ch = lane + 32 * k;
        float v = s[k] / (d[k >> 1] + 1e-16f) + bias[ch];
        hp[ch] = v > 0.f ? v : 0.f;              // relu after layer 1
    }
}

// ---------------- layer-2 aggregation + bias + log_softmax (48 channels, H=1) ----------------
__global__ __launch_bounds__(256) void k_agg2(const int* __restrict__ src,
                                              const int* __restrict__ eidx,
                                              const int* __restrict__ off,
                                              const int* __restrict__ cnt,
                                              const float* __restrict__ att,
                                              const float* __restrict__ bias,
                                              float* __restrict__ out) {
    int warp = (blockIdx.x * blockDim.x + threadIdx.x) >> 5;
    int lane = threadIdx.x & 31;
    if (warp >= N2v) return;

    bool v1ok = lane < 16;
    const float* xr = &g_xr2[(size_t)warp * OUTCv];
    float xr0 = xr[lane];
    float xr1 = v1ok ? xr[32 + lane] : 0.f;
    float at0 = att[lane];
    float at1 = v1ok ? att[32 + lane] : 0.f;
    float s0 = 0.f, s1 = 0.f, m = -1e30f, dd = 0.f;

    int a0 = off[warp], c = cnt[warp];
    for (int j = 0; j < c; j++) {
        int e  = eidx[a0 + j];
        int sn = src[e];
        const float* xlp = &g_xl2[(size_t)sn * OUTCv];
        float x0 = xlp[lane];
        float x1 = v1ok ? xlp[32 + lane] : 0.f;
        float e0 = x0 + xr0; e0 = e0 > 0.f ? e0 : 0.2f * e0;
        float e1 = x1 + xr1; e1 = e1 > 0.f ? e1 : 0.2f * e1;
        float p = e0 * at0 + (v1ok ? e1 * at1 : 0.f);
#pragma unroll
        for (int o = 16; o; o >>= 1) p += __shfl_xor_sync(0xffffffffu, p, o);
        float mn = fmaxf(m, p);
        float c1 = __expf(m - mn);
        float c2 = __expf(p - mn);
        dd = dd * c1 + c2;
        m = mn;
        s0 = s0 * c1 + c2 * x0;
        s1 = s1 * c1 + c2 * x1;
    }
    float inv = 1.f / (dd + 1e-16f);
    float v0 = s0 * inv + bias[lane];
    float v1 = v1ok ? s1 * inv + bias[32 + lane] : -1e30f;

    // log_softmax over 48 channels
    float mx = fmaxf(v0, v1);
#pragma unroll
    for (int o = 16; o; o >>= 1) mx = fmaxf(mx, __shfl_xor_sync(0xffffffffu, mx, o));
    float se = __expf(v0 - mx) + (v1ok ? __expf(v1 - mx) : 0.f);
#pragma unroll
    for (int o = 16; o; o >>= 1) se += __shfl_xor_sync(0xffffffffu, se, o);
    float lse = mx + logf(se);
    out[(size_t)warp * OUTCv + lane] = v0 - lse;
    if (v1ok) out[(size_t)warp * OUTCv + 32 + lane] = v1 - lse;
}

// ---------------- launch ----------------
static inline int cdiv(int a, int b) { return (a + b - 1) / b; }

extern "C" void kernel_launch(void* const* d_in, const int* in_sizes, int n_in,
                              void* d_out, int out_size) {
    const float* x     = (const float*)d_in[0];
    const float* Wl1   = (const float*)d_in[1];
    const float* bl1   = (const float*)d_in[2];
    const float* Wr1   = (const float*)d_in[3];
    const float* br1   = (const float*)d_in[4];
    const float* att1  = (const float*)d_in[5];
    const float* bias1 = (const float*)d_in[6];
    const float* Wl2   = (const float*)d_in[7];
    const float* bl2   = (const float*)d_in[8];
    const float* Wr2   = (const float*)d_in[9];
    const float* br2   = (const float*)d_in[10];
    const float* att2  = (const float*)d_in[11];
    const float* bias2 = (const float*)d_in[12];
    const int*   src1  = (const int*)d_in[13];
    const int*   dst1  = (const int*)d_in[14];
    const int*   src2  = (const int*)d_in[15];
    const int*   dst2  = (const int*)d_in[16];
    float* out = (float*)d_out;

    float *xl1, *xr1, *hbuf, *xl2, *xr2;
    int *cnt1, *off1, *cur1, *cnt2, *off2, *cur2, *eidx1, *eidx2, *part1, *part2;
    cudaGetSymbolAddress((void**)&xl1,   g_xl1);
    cudaGetSymbolAddress((void**)&xr1,   g_xr1);
    cudaGetSymbolAddress((void**)&hbuf,  g_h);
    cudaGetSymbolAddress((void**)&xl2,   g_xl2);
    cudaGetSymbolAddress((void**)&xr2,   g_xr2);
    cudaGetSymbolAddress((void**)&cnt1,  g_cnt1);
    cudaGetSymbolAddress((void**)&off1,  g_off1);
    cudaGetSymbolAddress((void**)&cur1,  g_cur1);
    cudaGetSymbolAddress((void**)&cnt2,  g_cnt2);
    cudaGetSymbolAddress((void**)&off2,  g_off2);
    cudaGetSymbolAddress((void**)&cur2,  g_cur2);
    cudaGetSymbolAddress((void**)&eidx1, g_eidx1);
    cudaGetSymbolAddress((void**)&eidx2, g_eidx2);
    cudaGetSymbolAddress((void**)&part1, g_part1);
    cudaGetSymbolAddress((void**)&part2, g_part2);

    // ---- CSR build for layer 1 (independent of GEMMs) ----
    k_zero<<<cdiv(N1v, 256), 256>>>(cnt1, N1v);
    k_zero<<<cdiv(N1v, 256), 256>>>(cur1, N1v);
    k_count<<<cdiv(E1v, 256), 256>>>(dst1, cnt1, E1v);
    int nb1 = cdiv(N1v, 1024);
    k_scan_block<<<nb1, 1024>>>(cnt1, off1, part1, N1v);
    k_scan_part<<<1, 1024>>>(part1, nb1);
    k_scan_add<<<nb1, 1024>>>(off1, part1, N1v);
    k_scatter<<<cdiv(E1v, 256), 256>>>(dst1, off1, cur1, eidx1, E1v);
    k_sort<<<cdiv(N1v, 256), 256>>>(off1, cnt1, eidx1, N1v);

    // ---- layer-1 transforms ----
    gemm_bias<<<dim3(cdiv(D1v, 128), cdiv(N0v, 128)), 256>>>(x, Wl1, bl1, xl1, N0v, D1v, INCv);
    gemm_bias<<<dim3(cdiv(D1v, 128), cdiv(N1v, 128)), 256>>>(x, Wr1, br1, xr1, N1v, D1v, INCv);

    // ---- layer-1 softmax-aggregate + relu ----
    k_agg1<<<cdiv(N1v * 32, 256), 256>>>(src1, eidx1, off1, cnt1, att1, bias1);

    // ---- CSR build for layer 2 ----
    k_zero<<<cdiv(N2v, 256), 256>>>(cnt2, N2v);
    k_zero<<<cdiv(N2v, 256), 256>>>(cur2, N2v);
    k_count<<<cdiv(E2v, 256), 256>>>(dst2, cnt2, E2v);
    int nb2 = cdiv(N2v, 1024);
    k_scan_block<<<nb2, 1024>>>(cnt2, off2, part2, N2v);
    k_scan_part<<<1, 1024>>>(part2, nb2);
    k_scan_add<<<nb2, 1024>>>(off2, part2, N2v);
    k_scatter<<<cdiv(E2v, 256), 256>>>(dst2, off2, cur2, eidx2, E2v);
    k_sort<<<cdiv(N2v, 256), 256>>>(off2, cnt2, eidx2, N2v);

    // ---- layer-2 transforms ----
    gemm_bias<<<dim3(cdiv(OUTCv, 128), cdiv(N1v, 128)), 256>>>(hbuf, Wl2, bl2, xl2, N1v, OUTCv, D1v);
    gemm_bias<<<dim3(cdiv(OUTCv, 128), cdiv(N2v, 128)), 256>>>(hbuf, Wr2, br2, xr2, N2v, OUTCv, D1v);

    // ---- layer-2 softmax-aggregate + bias + log_softmax ----
    k_agg2<<<cdiv(N2v * 32, 256), 256>>>(src2, eidx2, off2, cnt2, att2, bias2, out);

    (void)in_sizes; (void)n_in; (void)out_size;
}

// round 5
// speedup vs baseline: 1.5916x; 1.5916x over previous
#include <cuda_runtime.h>
#include <cuda_bf16.h>
#include <cstdint>
#include <cstddef>

// ---------------- problem constants ----------------
#define N0v   320000
#define N1v   80000
#define N2v   16000
#define E1v   800000
#define E2v   160000
#define INCv  128
#define HIDv  64
#define H1c   4
#define OUTCv 48
#define D1v   (H1c*HIDv)   // 256

// ---------------- scratch (device globals; no allocations allowed) ----------------
__device__ __nv_bfloat16 g_xcat[(size_t)N0v * 2 * INCv];   // x split hi|lo
__device__ float g_xl1[(size_t)N0v * D1v];                 // x @ Wl1 + bl1
__device__ float g_xr1[(size_t)N1v * D1v];                 // x[:N1] @ Wr1
__device__ __nv_bfloat16 g_hcat[(size_t)N1v * 2 * D1v];    // relu(h) split
__device__ float g_xl2[(size_t)N1v * OUTCv];
__device__ float g_xr2[(size_t)N2v * OUTCv];
__device__ __nv_bfloat16 g_B1l[(size_t)D1v * 2 * INCv];    // Wl1^T split [256][256]
__device__ __nv_bfloat16 g_B1r[(size_t)D1v * 2 * INCv];
__device__ __nv_bfloat16 g_B2l[(size_t)OUTCv * 2 * D1v];   // Wl2^T split [48][512]
__device__ __nv_bfloat16 g_B2r[(size_t)OUTCv * 2 * D1v];

__device__ int g_cnt1[N1v], g_off1[N1v], g_cur1[N1v];
__device__ int g_cnt2[N2v], g_off2[N2v], g_cur2[N2v];
__device__ int g_eidx1[E1v], g_eidx2[E2v];
__device__ int g_part1[256], g_part2[256];

// ---------------- PTX helpers (arch-agnostic: ldmatrix / mma.sync / cp.async) ----------------
__device__ __forceinline__ uint32_t smem_u32(const void* p) {
    uint32_t a;
    asm("{ .reg .u64 t; cvta.to.shared.u64 t, %1; cvt.u32.u64 %0, t; }" : "=r"(a) : "l"(p));
    return a;
}
__device__ __forceinline__ void ldmatrix_x4(uint32_t* r, uint32_t addr) {
    asm volatile("ldmatrix.sync.aligned.m8n8.x4.shared.b16 {%0,%1,%2,%3}, [%4];"
                 : "=r"(r[0]), "=r"(r[1]), "=r"(r[2]), "=r"(r[3]) : "r"(addr));
}
__device__ __forceinline__ void mma_bf16(float* c, const uint32_t* a, uint32_t b0, uint32_t b1) {
    asm volatile("mma.sync.aligned.m16n8k16.row.col.f32.bf16.bf16.f32 "
                 "{%0,%1,%2,%3}, {%4,%5,%6,%7}, {%8,%9}, {%0,%1,%2,%3};"
                 : "+f"(c[0]), "+f"(c[1]), "+f"(c[2]), "+f"(c[3])
                 : "r"(a[0]), "r"(a[1]), "r"(a[2]), "r"(a[3]), "r"(b0), "r"(b1));
}
__device__ __forceinline__ void cp_async16(uint32_t saddr, const void* gptr) {
    asm volatile("cp.async.cg.shared.global [%0], [%1], 16;" :: "r"(saddr), "l"(gptr));
}
#define CP_COMMIT() asm volatile("cp.async.commit_group;" ::: "memory")
#define CP_WAIT(n)  asm volatile("cp.async.wait_group %0;" :: "n"(n) : "memory")

// ---------------- bf16 split conversion kernels ----------------
__global__ void k_split(const float* __restrict__ in, __nv_bfloat16* __restrict__ out,
                        int n, int K) {
    int i = blockIdx.x * blockDim.x + threadIdx.x;
    if (i >= n) return;
    int r = i / K, c = i % K;
    float v = in[i];
    __nv_bfloat16 h = __float2bfloat16(v);
    __nv_bfloat16 l = __float2bfloat16(v - __bfloat162float(h));
    out[(size_t)r * 2 * K + c] = h;
    out[(size_t)r * 2 * K + K + c] = l;
}
// W [K,N] fp32 -> Bcat [N][2K] bf16 (transposed split)
__global__ void k_splitW(const float* __restrict__ W, __nv_bfloat16* __restrict__ out,
                         int K, int N) {
    int i = blockIdx.x * blockDim.x + threadIdx.x;
    if (i >= K * N) return;
    int k = i / N, n = i % N;
    float v = W[i];
    __nv_bfloat16 h = __float2bfloat16(v);
    __nv_bfloat16 l = __float2bfloat16(v - __bfloat162float(h));
    out[(size_t)n * 2 * K + k] = h;
    out[(size_t)n * 2 * K + K + k] = l;
}

// ---------------- HMMA GEMM: C[M,N_] = Acat@Bcat^T + bias ----------------
// Acat [M][2K] bf16 (hi|lo), Bcat [N_][2K] bf16 (hi|lo).
// D = Ah Bh + Ah Bl + Al Bh  (3 K-passes). Persistent CTAs, B stationary in SMEM,
// A staged per 32-K chunk through a 2-stage cp.async ring.
template <int N_, int K_>
__global__ __launch_bounds__(512) void gemm_mma(const __nv_bfloat16* __restrict__ Acat,
                                                const __nv_bfloat16* __restrict__ Bcat,
                                                const float* __restrict__ bias,
                                                float* __restrict__ C, int M) {
    constexpr int NB  = (N_ + 63) & ~63;     // padded N
    constexpr int KC2 = 2 * K_;
    constexpr int LDB = KC2 + 8;             // bf16 stride (B smem)
    constexpr int LDA = 40;                  // 32 + 8 pad
    constexpr int KP  = K_ / 32;             // chunks per pass
    constexpr int CH  = 3 * KP;              // total chunks
    constexpr int WN  = NB / 4;              // warp n-width
    constexpr int NT  = WN / 8;              // n8 tiles per warp
    constexpr int NPAIR = NT / 2;

    extern __shared__ char smem[];
    __nv_bfloat16* Bs = reinterpret_cast<__nv_bfloat16*>(smem);
    const uint32_t sBs = smem_u32(smem);
    const uint32_t sAs = sBs + NB * LDB * 2;

    const int tid = threadIdx.x, lid = tid & 31, wid = tid >> 5;
    const int wm = wid >> 2, wn = wid & 3;

    // ---- load stationary B (zero-pad rows >= N_) ----
    for (int i = tid; i < NB * (KC2 / 8); i += 512) {
        int row = i / (KC2 / 8), v = (i % (KC2 / 8)) * 8;
        uint4 val = make_uint4(0u, 0u, 0u, 0u);
        if (row < N_) val = *reinterpret_cast<const uint4*>(&Bcat[(size_t)row * KC2 + v]);
        *reinterpret_cast<uint4*>(&Bs[row * LDB + v]) = val;
    }
    __syncthreads();

    const int nTiles = M / 128;
    for (int t = blockIdx.x; t < nTiles; t += gridDim.x) {
        const size_t m0 = (size_t)t * 128;
        float acc[2][NT][4];
#pragma unroll
        for (int i = 0; i < 2; i++)
#pragma unroll
            for (int j = 0; j < NT; j++)
#pragma unroll
                for (int q = 0; q < 4; q++) acc[i][j][q] = 0.f;

        // issue chunk 0
        {
            const int p = 0, kk = 0;
            const int ak = (p == 2 ? K_ : 0) + kk;
            int row = tid >> 2, v = (tid & 3) * 8;
            cp_async16(sAs + 2 * (row * LDA + v),
                       &Acat[(m0 + row) * KC2 + ak + v]);
            CP_COMMIT();
        }

        for (int c = 0; c < CH; c++) {
            if (c + 1 < CH) {
                const int cn = c + 1;
                const int p = cn / KP, kk = (cn % KP) * 32;
                const int ak = (p == 2 ? K_ : 0) + kk;
                const int st = cn & 1;
                int row = tid >> 2, v = (tid & 3) * 8;
                cp_async16(sAs + 2 * (st * 128 * LDA + row * LDA + v),
                           &Acat[(m0 + row) * KC2 + ak + v]);
                CP_COMMIT();
                CP_WAIT(1);
            } else {
                CP_WAIT(0);
            }
            __syncthreads();

            const int p  = c / KP, kk = (c % KP) * 32;
            const int bk = (p == 1 ? K_ : 0) + kk;
            const int stageOff = (c & 1) * 128 * LDA;
#pragma unroll
            for (int kt = 0; kt < 2; kt++) {
                uint32_t a[2][4];
#pragma unroll
                for (int mt = 0; mt < 2; mt++) {
                    uint32_t addr = sAs + 2 * (stageOff +
                        (wm * 32 + mt * 16 + (lid & 15)) * LDA + kt * 16 + (lid >> 4) * 8);
                    ldmatrix_x4(a[mt], addr);
                }
#pragma unroll
                for (int np = 0; np < NPAIR; np++) {
                    uint32_t b[4];
                    int g = lid >> 3;
                    int nrow = wn * WN + np * 16 + ((g >> 1) << 3) + (lid & 7);
                    int col  = bk + kt * 16 + ((g & 1) << 3);
                    ldmatrix_x4(b, sBs + 2 * (nrow * LDB + col));
                    mma_bf16(acc[0][np * 2 + 0], a[0], b[0], b[1]);
                    mma_bf16(acc[0][np * 2 + 1], a[0], b[2], b[3]);
                    mma_bf16(acc[1][np * 2 + 0], a[1], b[0], b[1]);
                    mma_bf16(acc[1][np * 2 + 1], a[1], b[2], b[3]);
                }
            }
            __syncthreads();
        }

        // ---- epilogue: bias + store ----
#pragma unroll
        for (int mt = 0; mt < 2; mt++) {
#pragma unroll
            for (int nt = 0; nt < NT; nt++) {
                int colb = wn * WN + nt * 8 + (lid & 3) * 2;
                if (colb < N_) {
                    size_t r0 = m0 + wm * 32 + mt * 16 + (lid >> 2);
                    float2 v0 = make_float2(acc[mt][nt][0] + bias[colb],
                                            acc[mt][nt][1] + bias[colb + 1]);
                    float2 v1 = make_float2(acc[mt][nt][2] + bias[colb],
                                            acc[mt][nt][3] + bias[colb + 1]);
                    *reinterpret_cast<float2*>(&C[r0 * N_ + colb]) = v0;
                    *reinterpret_cast<float2*>(&C[(r0 + 8) * N_ + colb]) = v1;
                }
            }
        }
        __syncthreads();   // all warps done with As before next tile's chunk-0 issue
    }
}

// ---------------- CSR build helpers ----------------
__global__ void k_zero(int* p, int n) {
    int i = blockIdx.x * blockDim.x + threadIdx.x;
    if (i < n) p[i] = 0;
}
__global__ void k_count(const int* __restrict__ dst, int* __restrict__ cnt, int E) {
    int e = blockIdx.x * blockDim.x + threadIdx.x;
    if (e < E) atomicAdd(&cnt[dst[e]], 1);
}
__global__ __launch_bounds__(1024) void k_scan_block(const int* __restrict__ in,
                                                     int* __restrict__ out,
                                                     int* __restrict__ part, int n) {
    __shared__ int sh[1024];
    int t = threadIdx.x;
    int i = blockIdx.x * 1024 + t;
    int v = (i < n) ? in[i] : 0;
    sh[t] = v;
    __syncthreads();
    for (int d = 1; d < 1024; d <<= 1) {
        int add = (t >= d) ? sh[t - d] : 0;
        __syncthreads();
        sh[t] += add;
        __syncthreads();
    }
    if (i < n) out[i] = sh[t] - v;
    if (t == 1023) part[blockIdx.x] = sh[1023];
}
__global__ __launch_bounds__(1024) void k_scan_part(int* part, int nb) {
    __shared__ int sh[1024];
    int t = threadIdx.x;
    int v = (t < nb) ? part[t] : 0;
    sh[t] = v;
    __syncthreads();
    for (int d = 1; d < 1024; d <<= 1) {
        int add = (t >= d) ? sh[t - d] : 0;
        __syncthreads();
        sh[t] += add;
        __syncthreads();
    }
    if (t < nb) part[t] = sh[t] - v;
}
__global__ __launch_bounds__(1024) void k_scan_add(int* out, const int* part, int n) {
    int i = blockIdx.x * 1024 + threadIdx.x;
    if (i < n) out[i] += part[blockIdx.x];
}
__global__ void k_scatter(const int* __restrict__ dst, const int* __restrict__ off,
                          int* __restrict__ cur, int* __restrict__ eidx, int E) {
    int e = blockIdx.x * blockDim.x + threadIdx.x;
    if (e < E) {
        int d = dst[e];
        int p = off[d] + atomicAdd(&cur[d], 1);
        eidx[p] = e;
    }
}
__global__ void k_sort(const int* __restrict__ off, const int* __restrict__ cnt,
                       int* __restrict__ eidx, int n) {
    int i = blockIdx.x * blockDim.x + threadIdx.x;
    if (i >= n) return;
    int a = off[i], c = cnt[i];
    for (int x = 1; x < c; x++) {
        int key = eidx[a + x];
        int y = x - 1;
        while (y >= 0 && eidx[a + y] > key) { eidx[a + y + 1] = eidx[a + y]; y--; }
        eidx[a + y + 1] = key;
    }
}

// ---------------- layer-1 aggregation: warp/dst node, online softmax; writes bf16 split h ----------------
__global__ __launch_bounds__(256) void k_agg1(const int* __restrict__ src,
                                              const int* __restrict__ eidx,
                                              const int* __restrict__ off,
                                              const int* __restrict__ cnt,
                                              const float* __restrict__ att,
                                              const float* __restrict__ bias) {
    int warp = (blockIdx.x * blockDim.x + threadIdx.x) >> 5;
    int lane = threadIdx.x & 31;
    if (warp >= N1v) return;

    const float* xr = &g_xr1[(size_t)warp * D1v];
    float xrr[8], attr[8], s[8], m[4], d[4];
#pragma unroll
    for (int k = 0; k < 8; k++) {
        int ch = lane + 32 * k;
        xrr[k] = xr[ch];
        attr[k] = att[ch];
        s[k] = 0.f;
    }
#pragma unroll
    for (int h = 0; h < 4; h++) { m[h] = -1e30f; d[h] = 0.f; }

    int a0 = off[warp], c = cnt[warp];
    for (int j = 0; j < c; j++) {
        int e  = eidx[a0 + j];
        int sn = src[e];
        const float* xlp = &g_xl1[(size_t)sn * D1v];
        float xl[8];
#pragma unroll
        for (int k = 0; k < 8; k++) xl[k] = xlp[lane + 32 * k];
#pragma unroll
        for (int h = 0; h < 4; h++) {
            float p = 0.f;
#pragma unroll
            for (int kk = 0; kk < 2; kk++) {
                int k = 2 * h + kk;
                float ev = xl[k] + xrr[k];
                ev = ev > 0.f ? ev : 0.2f * ev;
                p += ev * attr[k];
            }
#pragma unroll
            for (int o = 16; o; o >>= 1) p += __shfl_xor_sync(0xffffffffu, p, o);
            float mn = fmaxf(m[h], p);
            float c1 = __expf(m[h] - mn);
            float c2 = __expf(p - mn);
            d[h] = d[h] * c1 + c2;
            m[h] = mn;
#pragma unroll
            for (int kk = 0; kk < 2; kk++) {
                int k = 2 * h + kk;
                s[k] = s[k] * c1 + c2 * xl[k];
            }
        }
    }
    __nv_bfloat16* hp = &g_hcat[(size_t)warp * 2 * D1v];
#pragma unroll
    for (int k = 0; k < 8; k++) {
        int ch = lane + 32 * k;
        float v = s[k] / (d[k >> 1] + 1e-16f) + bias[ch];
        v = v > 0.f ? v : 0.f;                      // relu
        __nv_bfloat16 hi = __float2bfloat16(v);
        __nv_bfloat16 lo = __float2bfloat16(v - __bfloat162float(hi));
        hp[ch] = hi;
        hp[D1v + ch] = lo;
    }
}

// ---------------- layer-2 aggregation + bias + log_softmax ----------------
__global__ __launch_bounds__(256) void k_agg2(const int* __restrict__ src,
                                              const int* __restrict__ eidx,
                                              const int* __restrict__ off,
                                              const int* __restrict__ cnt,
                                              const float* __restrict__ att,
                                              const float* __restrict__ bias,
                                              float* __restrict__ out) {
    int warp = (blockIdx.x * blockDim.x + threadIdx.x) >> 5;
    int lane = threadIdx.x & 31;
    if (warp >= N2v) return;

    bool v1ok = lane < 16;
    const float* xr = &g_xr2[(size_t)warp * OUTCv];
    float xr0 = xr[lane];
    float xr1 = v1ok ? xr[32 + lane] : 0.f;
    float at0 = att[lane];
    float at1 = v1ok ? att[32 + lane] : 0.f;
    float s0 = 0.f, s1 = 0.f, m = -1e30f, dd = 0.f;

    int a0 = off[warp], c = cnt[warp];
    for (int j = 0; j < c; j++) {
        int e  = eidx[a0 + j];
        int sn = src[e];
        const float* xlp = &g_xl2[(size_t)sn * OUTCv];
        float x0 = xlp[lane];
        float x1 = v1ok ? xlp[32 + lane] : 0.f;
        float e0 = x0 + xr0; e0 = e0 > 0.f ? e0 : 0.2f * e0;
        float e1 = x1 + xr1; e1 = e1 > 0.f ? e1 : 0.2f * e1;
        float p = e0 * at0 + (v1ok ? e1 * at1 : 0.f);
#pragma unroll
        for (int o = 16; o; o >>= 1) p += __shfl_xor_sync(0xffffffffu, p, o);
        float mn = fmaxf(m, p);
        float c1 = __expf(m - mn);
        float c2 = __expf(p - mn);
        dd = dd * c1 + c2;
        m = mn;
        s0 = s0 * c1 + c2 * x0;
        s1 = s1 * c1 + c2 * x1;
    }
    float inv = 1.f / (dd + 1e-16f);
    float v0 = s0 * inv + bias[lane];
    float v1 = v1ok ? s1 * inv + bias[32 + lane] : -1e30f;

    float mx = fmaxf(v0, v1);
#pragma unroll
    for (int o = 16; o; o >>= 1) mx = fmaxf(mx, __shfl_xor_sync(0xffffffffu, mx, o));
    float se = __expf(v0 - mx) + (v1ok ? __expf(v1 - mx) : 0.f);
#pragma unroll
    for (int o = 16; o; o >>= 1) se += __shfl_xor_sync(0xffffffffu, se, o);
    float lse = mx + logf(se);
    out[(size_t)warp * OUTCv + lane] = v0 - lse;
    if (v1ok) out[(size_t)warp * OUTCv + 32 + lane] = v1 - lse;
}

// ---------------- launch ----------------
static inline int cdiv(int a, int b) { return (a + b - 1) / b; }

extern "C" void kernel_launch(void* const* d_in, const int* in_sizes, int n_in,
                              void* d_out, int out_size) {
    const float* x     = (const float*)d_in[0];
    const float* Wl1   = (const float*)d_in[1];
    const float* bl1   = (const float*)d_in[2];
    const float* Wr1   = (const float*)d_in[3];
    const float* br1   = (const float*)d_in[4];
    const float* att1  = (const float*)d_in[5];
    const float* bias1 = (const float*)d_in[6];
    const float* Wl2   = (const float*)d_in[7];
    const float* bl2   = (const float*)d_in[8];
    const float* Wr2   = (const float*)d_in[9];
    const float* br2   = (const float*)d_in[10];
    const float* att2  = (const float*)d_in[11];
    const float* bias2 = (const float*)d_in[12];
    const int*   src1  = (const int*)d_in[13];
    const int*   dst1  = (const int*)d_in[14];
    const int*   src2  = (const int*)d_in[15];
    const int*   dst2  = (const int*)d_in[16];
    float* out = (float*)d_out;

    __nv_bfloat16 *xcat, *hcat, *B1l, *B1r, *B2l, *B2r;
    float *xl1, *xr1, *xl2, *xr2;
    int *cnt1, *off1, *cur1, *cnt2, *off2, *cur2, *eidx1, *eidx2, *part1, *part2;
    cudaGetSymbolAddress((void**)&xcat,  g_xcat);
    cudaGetSymbolAddress((void**)&hcat,  g_hcat);
    cudaGetSymbolAddress((void**)&B1l,   g_B1l);
    cudaGetSymbolAddress((void**)&B1r,   g_B1r);
    cudaGetSymbolAddress((void**)&B2l,   g_B2l);
    cudaGetSymbolAddress((void**)&B2r,   g_B2r);
    cudaGetSymbolAddress((void**)&xl1,   g_xl1);
    cudaGetSymbolAddress((void**)&xr1,   g_xr1);
    cudaGetSymbolAddress((void**)&xl2,   g_xl2);
    cudaGetSymbolAddress((void**)&xr2,   g_xr2);
    cudaGetSymbolAddress((void**)&cnt1,  g_cnt1);
    cudaGetSymbolAddress((void**)&off1,  g_off1);
    cudaGetSymbolAddress((void**)&cur1,  g_cur1);
    cudaGetSymbolAddress((void**)&cnt2,  g_cnt2);
    cudaGetSymbolAddress((void**)&off2,  g_off2);
    cudaGetSymbolAddress((void**)&cur2,  g_cur2);
    cudaGetSymbolAddress((void**)&eidx1, g_eidx1);
    cudaGetSymbolAddress((void**)&eidx2, g_eidx2);
    cudaGetSymbolAddress((void**)&part1, g_part1);
    cudaGetSymbolAddress((void**)&part2, g_part2);

    // SMEM: Bs (NB*LDB*2) + As ring (2*128*40*2)
    const int SMEM1 = 256 * (2 * 128 + 8) * 2 + 2 * 128 * 40 * 2;   // 155648
    const int SMEM2 = 64  * (2 * 256 + 8) * 2 + 2 * 128 * 40 * 2;   // 87040
    cudaFuncSetAttribute(gemm_mma<256, 128>, cudaFuncAttributeMaxDynamicSharedMemorySize, SMEM1);
    cudaFuncSetAttribute(gemm_mma<48, 256>,  cudaFuncAttributeMaxDynamicSharedMemorySize, SMEM2);

    // ---- CSR build for layer 1 ----
    k_zero<<<cdiv(N1v, 256), 256>>>(cnt1, N1v);
    k_zero<<<cdiv(N1v, 256), 256>>>(cur1, N1v);
    k_count<<<cdiv(E1v, 256), 256>>>(dst1, cnt1, E1v);
    int nb1 = cdiv(N1v, 1024);
    k_scan_block<<<nb1, 1024>>>(cnt1, off1, part1, N1v);
    k_scan_part<<<1, 1024>>>(part1, nb1);
    k_scan_add<<<nb1, 1024>>>(off1, part1, N1v);
    k_scatter<<<cdiv(E1v, 256), 256>>>(dst1, off1, cur1, eidx1, E1v);
    k_sort<<<cdiv(N1v, 256), 256>>>(off1, cnt1, eidx1, N1v);

    // ---- bf16 splits ----
    k_split<<<cdiv(N0v * INCv, 256), 256>>>(x, xcat, N0v * INCv, INCv);
    k_splitW<<<cdiv(INCv * D1v, 256), 256>>>(Wl1, B1l, INCv, D1v);
    k_splitW<<<cdiv(INCv * D1v, 256), 256>>>(Wr1, B1r, INCv, D1v);
    k_splitW<<<cdiv(D1v * OUTCv, 256), 256>>>(Wl2, B2l, D1v, OUTCv);
    k_splitW<<<cdiv(D1v * OUTCv, 256), 256>>>(Wr2, B2r, D1v, OUTCv);

    // ---- layer-1 transforms (HMMA) ----
    gemm_mma<256, 128><<<148, 512, SMEM1>>>(xcat, B1l, bl1, xl1, N0v);
    gemm_mma<256, 128><<<148, 512, SMEM1>>>(xcat, B1r, br1, xr1, N1v);

    // ---- layer-1 softmax-aggregate + relu (-> bf16 split h) ----
    k_agg1<<<cdiv(N1v * 32, 256), 256>>>(src1, eidx1, off1, cnt1, att1, bias1);

    // ---- CSR build for layer 2 ----
    k_zero<<<cdiv(N2v, 256), 256>>>(cnt2, N2v);
    k_zero<<<cdiv(N2v, 256), 256>>>(cur2, N2v);
    k_count<<<cdiv(E2v, 256), 256>>>(dst2, cnt2, E2v);
    int nb2 = cdiv(N2v, 1024);
    k_scan_block<<<nb2, 1024>>>(cnt2, off2, part2, N2v);
    k_scan_part<<<1, 1024>>>(part2, nb2);
    k_scan_add<<<nb2, 1024>>>(off2, part2, N2v);
    k_scatter<<<cdiv(E2v, 256), 256>>>(dst2, off2, cur2, eidx2, E2v);
    k_sort<<<cdiv(N2v, 256), 256>>>(off2, cnt2, eidx2, N2v);

    // ---- layer-2 transforms (HMMA) ----
    gemm_mma<48, 256><<<148, 512, SMEM2>>>(hcat, B2l, bl2, xl2, N1v);
    gemm_mma<48, 256><<<125, 512, SMEM2>>>(hcat, B2r, br2, xr2, N2v);

    // ---- layer-2 softmax-aggregate + bias + log_softmax ----
    k_agg2<<<cdiv(N2v * 32, 256), 256>>>(src2, eidx2, off2, cnt2, att2, bias2, out);

    (void)in_sizes; (void)n_in; (void)out_size;
}

// round 7
// speedup vs baseline: 1.6349x; 1.0272x over previous
#include <cuda_runtime.h>
#include <cuda_bf16.h>
#include <cuda_fp16.h>
#include <cstdint>
#include <cstddef>

// ---------------- problem constants ----------------
#define N0v   320000
#define N1v   80000
#define N2v   16000
#define E1v   800000
#define E2v   160000
#define INCv  128
#define HIDv  64
#define H1c   4
#define OUTCv 48
#define D1v   (H1c*HIDv)   // 256

// ---------------- scratch (device globals) ----------------
__device__ __nv_bfloat16 g_xcat[(size_t)N0v * 2 * INCv];   // x split hi|lo
__device__ __half g_xl1[(size_t)N0v * D1v];                // fp16 x@Wl1+bl1
__device__ __half g_xr1[(size_t)N1v * D1v];
__device__ __nv_bfloat16 g_hcat[(size_t)N1v * 2 * D1v];    // relu(h) split
__device__ __half g_xl2[(size_t)N1v * OUTCv];
__device__ __half g_xr2[(size_t)N2v * OUTCv];
__device__ __nv_bfloat16 g_B1l[(size_t)D1v * 2 * INCv];    // Wl1^T split [256][256]
__device__ __nv_bfloat16 g_B1r[(size_t)D1v * 2 * INCv];
__device__ __nv_bfloat16 g_B2l[(size_t)OUTCv * 2 * D1v];   // Wl2^T split [48][512]
__device__ __nv_bfloat16 g_B2r[(size_t)OUTCv * 2 * D1v];

__device__ int g_cnt1[N1v], g_off1[N1v], g_cur1[N1v];
__device__ int g_cnt2[N2v], g_off2[N2v], g_cur2[N2v];
__device__ int g_eidx1[E1v], g_eidx2[E2v];
__device__ int g_part1[256], g_part2[256];

// ---------------- PTX helpers ----------------
__device__ __forceinline__ uint32_t smem_u32(const void* p) {
    uint32_t a;
    asm("{ .reg .u64 t; cvta.to.shared.u64 t, %1; cvt.u32.u64 %0, t; }" : "=r"(a) : "l"(p));
    return a;
}
__device__ __forceinline__ void ldmatrix_x4(uint32_t* r, uint32_t addr) {
    asm volatile("ldmatrix.sync.aligned.m8n8.x4.shared.b16 {%0,%1,%2,%3}, [%4];"
                 : "=r"(r[0]), "=r"(r[1]), "=r"(r[2]), "=r"(r[3]) : "r"(addr));
}
__device__ __forceinline__ void mma_bf16(float* c, const uint32_t* a, uint32_t b0, uint32_t b1) {
    asm volatile("mma.sync.aligned.m16n8k16.row.col.f32.bf16.bf16.f32 "
                 "{%0,%1,%2,%3}, {%4,%5,%6,%7}, {%8,%9}, {%0,%1,%2,%3};"
                 : "+f"(c[0]), "+f"(c[1]), "+f"(c[2]), "+f"(c[3])
                 : "r"(a[0]), "r"(a[1]), "r"(a[2]), "r"(a[3]), "r"(b0), "r"(b1));
}
__device__ __forceinline__ void cp_async16(uint32_t saddr, const void* gptr) {
    asm volatile("cp.async.cg.shared.global [%0], [%1], 16;" :: "r"(saddr), "l"(gptr));
}
#define CP_COMMIT() asm volatile("cp.async.commit_group;" ::: "memory")
#define CP_WAIT(n)  asm volatile("cp.async.wait_group %0;" :: "n"(n) : "memory")

// ---------------- bf16 split conversions ----------------
__global__ void k_split(const float* __restrict__ in, __nv_bfloat16* __restrict__ out,
                        int n, int K) {
    int i = blockIdx.x * blockDim.x + threadIdx.x;
    if (i >= n) return;
    int r = i / K, c = i % K;
    float v = in[i];
    __nv_bfloat16 h = __float2bfloat16(v);
    __nv_bfloat16 l = __float2bfloat16(v - __bfloat162float(h));
    out[(size_t)r * 2 * K + c] = h;
    out[(size_t)r * 2 * K + K + c] = l;
}
// fused weight split for all 4 weight matrices
__global__ void k_splitW_all(const float* __restrict__ Wl1, const float* __restrict__ Wr1,
                             const float* __restrict__ Wl2, const float* __restrict__ Wr2) {
    const int S1 = INCv * D1v;     // 32768
    const int S2 = D1v * OUTCv;    // 12288
    int i = blockIdx.x * blockDim.x + threadIdx.x;
    const float* W; __nv_bfloat16* out; int K, N, j;
    if (i < S1)               { W = Wl1; out = g_B1l; K = INCv; N = D1v;  j = i; }
    else if (i < 2 * S1)      { W = Wr1; out = g_B1r; K = INCv; N = D1v;  j = i - S1; }
    else if (i < 2 * S1 + S2) { W = Wl2; out = g_B2l; K = D1v;  N = OUTCv; j = i - 2 * S1; }
    else if (i < 2 * (S1 + S2)) { W = Wr2; out = g_B2r; K = D1v; N = OUTCv; j = i - 2 * S1 - S2; }
    else return;
    int k = j / N, n = j % N;
    float v = W[j];
    __nv_bfloat16 h = __float2bfloat16(v);
    __nv_bfloat16 l = __float2bfloat16(v - __bfloat162float(h));
    out[(size_t)n * 2 * K + k] = h;
    out[(size_t)n * 2 * K + K + k] = l;
}

// ---------------- HMMA GEMM: C[M,N_] = Acat@Bcat^T + bias (fp16 out) ----------------
template <int N_, int K_>
__global__ __launch_bounds__(512) void gemm_mma(const __nv_bfloat16* __restrict__ Acat,
                                                const __nv_bfloat16* __restrict__ Bcat,
                                                const float* __restrict__ bias,
                                                __half* __restrict__ C, int M) {
    constexpr int NB  = (N_ + 63) & ~63;
    constexpr int KC2 = 2 * K_;
    constexpr int LDB = KC2 + 8;
    constexpr int LDA = 40;
    constexpr int KP  = K_ / 32;
    constexpr int CH  = 3 * KP;
    constexpr int WN  = NB / 4;
    constexpr int NT  = WN / 8;
    constexpr int NPAIR = NT / 2;

    extern __shared__ char smem[];
    __nv_bfloat16* Bs = reinterpret_cast<__nv_bfloat16*>(smem);
    const uint32_t sBs = smem_u32(smem);
    const uint32_t sAs = sBs + NB * LDB * 2;

    const int tid = threadIdx.x, lid = tid & 31, wid = tid >> 5;
    const int wm = wid >> 2, wn = wid & 3;

    for (int i = tid; i < NB * (KC2 / 8); i += 512) {
        int row = i / (KC2 / 8), v = (i % (KC2 / 8)) * 8;
        uint4 val = make_uint4(0u, 0u, 0u, 0u);
        if (row < N_) val = *reinterpret_cast<const uint4*>(&Bcat[(size_t)row * KC2 + v]);
        *reinterpret_cast<uint4*>(&Bs[row * LDB + v]) = val;
    }
    __syncthreads();

    const int nTiles = M / 128;
    for (int t = blockIdx.x; t < nTiles; t += gridDim.x) {
        const size_t m0 = (size_t)t * 128;
        float acc[2][NT][4];
#pragma unroll
        for (int i = 0; i < 2; i++)
#pragma unroll
            for (int j = 0; j < NT; j++)
#pragma unroll
                for (int q = 0; q < 4; q++) acc[i][j][q] = 0.f;

        {
            int row = tid >> 2, v = (tid & 3) * 8;
            cp_async16(sAs + 2 * (row * LDA + v), &Acat[(m0 + row) * KC2 + v]);
            CP_COMMIT();
        }

        for (int c = 0; c < CH; c++) {
            if (c + 1 < CH) {
                const int cn = c + 1;
                const int p = cn / KP, kk = (cn % KP) * 32;
                const int ak = (p == 2 ? K_ : 0) + kk;
                const int st = cn & 1;
                int row = tid >> 2, v = (tid & 3) * 8;
                cp_async16(sAs + 2 * (st * 128 * LDA + row * LDA + v),
                           &Acat[(m0 + row) * KC2 + ak + v]);
                CP_COMMIT();
                CP_WAIT(1);
            } else {
                CP_WAIT(0);
            }
            __syncthreads();

            const int p  = c / KP, kk = (c % KP) * 32;
            const int bk = (p == 1 ? K_ : 0) + kk;
            const int stageOff = (c & 1) * 128 * LDA;
#pragma unroll
            for (int kt = 0; kt < 2; kt++) {
                uint32_t a[2][4];
#pragma unroll
                for (int mt = 0; mt < 2; mt++) {
                    uint32_t addr = sAs + 2 * (stageOff +
                        (wm * 32 + mt * 16 + (lid & 15)) * LDA + kt * 16 + (lid >> 4) * 8);
                    ldmatrix_x4(a[mt], addr);
                }
#pragma unroll
                for (int np = 0; np < NPAIR; np++) {
                    uint32_t b[4];
                    int g = lid >> 3;
                    int nrow = wn * WN + np * 16 + ((g >> 1) << 3) + (lid & 7);
                    int col  = bk + kt * 16 + ((g & 1) << 3);
                    ldmatrix_x4(b, sBs + 2 * (nrow * LDB + col));
                    mma_bf16(acc[0][np * 2 + 0], a[0], b[0], b[1]);
                    mma_bf16(acc[0][np * 2 + 1], a[0], b[2], b[3]);
                    mma_bf16(acc[1][np * 2 + 0], a[1], b[0], b[1]);
                    mma_bf16(acc[1][np * 2 + 1], a[1], b[2], b[3]);
                }
            }
            __syncthreads();
        }

#pragma unroll
        for (int mt = 0; mt < 2; mt++) {
#pragma unroll
            for (int nt = 0; nt < NT; nt++) {
                int colb = wn * WN + nt * 8 + (lid & 3) * 2;
                if (colb < N_) {
                    size_t r0 = m0 + wm * 32 + mt * 16 + (lid >> 2);
                    float b0 = bias[colb], b1 = bias[colb + 1];
                    __half2 v0 = __floats2half2_rn(acc[mt][nt][0] + b0, acc[mt][nt][1] + b1);
                    __half2 v1 = __floats2half2_rn(acc[mt][nt][2] + b0, acc[mt][nt][3] + b1);
                    *reinterpret_cast<__half2*>(&C[r0 * N_ + colb]) = v0;
                    *reinterpret_cast<__half2*>(&C[(r0 + 8) * N_ + colb]) = v1;
                }
            }
        }
        __syncthreads();
    }
}

// ---------------- fused CSR build ----------------
__global__ void k_zero_all() {
    int i = blockIdx.x * blockDim.x + threadIdx.x;
    if (i < N1v) { g_cnt1[i] = 0; g_cur1[i] = 0; }
    if (i < N2v) { g_cnt2[i] = 0; g_cur2[i] = 0; }
}
__global__ void k_count_all(const int* __restrict__ dst1, const int* __restrict__ dst2) {
    int i = blockIdx.x * blockDim.x + threadIdx.x;
    if (i < E1v) atomicAdd(&g_cnt1[dst1[i]], 1);
    else if (i < E1v + E2v) atomicAdd(&g_cnt2[dst2[i - E1v]], 1);
}
__global__ __launch_bounds__(1024) void k_scan_block(const int* __restrict__ in,
                                                     int* __restrict__ out,
                                                     int* __restrict__ part, int n) {
    __shared__ int sh[1024];
    int t = threadIdx.x;
    int i = blockIdx.x * 1024 + t;
    int v = (i < n) ? in[i] : 0;
    sh[t] = v;
    __syncthreads();
    for (int d = 1; d < 1024; d <<= 1) {
        int add = (t >= d) ? sh[t - d] : 0;
        __syncthreads();
        sh[t] += add;
        __syncthreads();
    }
    if (i < n) out[i] = sh[t] - v;
    if (t == 1023) part[blockIdx.x] = sh[1023];
}
__global__ __launch_bounds__(1024) void k_scan_part(int* part, int nb) {
    __shared__ int sh[1024];
    int t = threadIdx.x;
    int v = (t < nb) ? part[t] : 0;
    sh[t] = v;
    __syncthreads();
    for (int d = 1; d < 1024; d <<= 1) {
        int add = (t >= d) ? sh[t - d] : 0;
        __syncthreads();
        sh[t] += add;
        __syncthreads();
    }
    if (t < nb) part[t] = sh[t] - v;
}
__global__ __launch_bounds__(1024) void k_scan_add(int* out, const int* part, int n) {
    int i = blockIdx.x * 1024 + threadIdx.x;
    if (i < n) out[i] += part[blockIdx.x];
}
__global__ void k_scatter_all(const int* __restrict__ dst1, const int* __restrict__ dst2) {
    int i = blockIdx.x * blockDim.x + threadIdx.x;
    if (i < E1v) {
        int d = dst1[i];
        g_eidx1[g_off1[d] + atomicAdd(&g_cur1[d], 1)] = i;
    } else if (i < E1v + E2v) {
        int e = i - E1v;
        int d = dst2[e];
        g_eidx2[g_off2[d] + atomicAdd(&g_cur2[d], 1)] = e;
    }
}
__global__ void k_sort_all() {
    int i = blockIdx.x * blockDim.x + threadIdx.x;
    int a, c; int* eidx;
    if (i < N1v) { a = g_off1[i]; c = g_cnt1[i]; eidx = g_eidx1; }
    else if (i < N1v + N2v) { int j = i - N1v; a = g_off2[j]; c = g_cnt2[j]; eidx = g_eidx2; }
    else return;
    for (int x = 1; x < c; x++) {
        int key = eidx[a + x];
        int y = x - 1;
        while (y >= 0 && eidx[a + y] > key) { eidx[a + y + 1] = eidx[a + y]; y--; }
        eidx[a + y + 1] = key;
    }
}

// ---------------- layer-1 aggregation (fp16 gather, online softmax) ----------------
// lane handles half2 idx = lane + 32*q; head = q; channels ch0=2*idx, ch0+1.
__global__ __launch_bounds__(256) void k_agg1(const int* __restrict__ src,
                                              const float* __restrict__ att,
                                              const float* __restrict__ bias) {
    int warp = (blockIdx.x * blockDim.x + threadIdx.x) >> 5;
    int lane = threadIdx.x & 31;
    if (warp >= N1v) return;

    const __half2* xr = reinterpret_cast<const __half2*>(&g_xr1[(size_t)warp * D1v]);
    float2 xrr[4], attr[4];
    float s0[4], s1[4], m[4], d[4];
#pragma unroll
    for (int q = 0; q < 4; q++) {
        int idx = lane + 32 * q;
        xrr[q] = __half22float2(xr[idx]);
        attr[q] = make_float2(att[2 * idx], att[2 * idx + 1]);
        s0[q] = 0.f; s1[q] = 0.f; m[q] = -1e30f; d[q] = 0.f;
    }

    int a0 = g_off1[warp], c = g_cnt1[warp];
    for (int j = 0; j < c; j++) {
        int sn = src[g_eidx1[a0 + j]];
        const __half2* xlp = reinterpret_cast<const __half2*>(&g_xl1[(size_t)sn * D1v]);
        float2 xl[4];
        float p[4];
#pragma unroll
        for (int q = 0; q < 4; q++) {
            xl[q] = __half22float2(xlp[lane + 32 * q]);
            float e0 = xl[q].x + xrr[q].x; e0 = e0 > 0.f ? e0 : 0.2f * e0;
            float e1 = xl[q].y + xrr[q].y; e1 = e1 > 0.f ? e1 : 0.2f * e1;
            p[q] = e0 * attr[q].x + e1 * attr[q].y;
        }
        // grouped reduction: 8 + 3 + 4 shuffles
#pragma unroll
        for (int q = 0; q < 4; q++) p[q] += __shfl_xor_sync(0xffffffffu, p[q], 16);
#pragma unroll
        for (int q = 0; q < 4; q++) p[q] += __shfl_xor_sync(0xffffffffu, p[q], 8);
        int g = lane >> 3;
        float v = (g == 0) ? p[0] : (g == 1) ? p[1] : (g == 2) ? p[2] : p[3];
        v += __shfl_xor_sync(0xffffffffu, v, 4);
        v += __shfl_xor_sync(0xffffffffu, v, 2);
        v += __shfl_xor_sync(0xffffffffu, v, 1);
#pragma unroll
        for (int q = 0; q < 4; q++) {
            float hq = __shfl_sync(0xffffffffu, v, q << 3);
            float mn = fmaxf(m[q], hq);
            float c1 = __expf(m[q] - mn);
            float c2 = __expf(hq - mn);
            d[q] = d[q] * c1 + c2;
            m[q] = mn;
            s0[q] = s0[q] * c1 + c2 * xl[q].x;
            s1[q] = s1[q] * c1 + c2 * xl[q].y;
        }
    }
    __nv_bfloat16* hp = &g_hcat[(size_t)warp * 2 * D1v];
#pragma unroll
    for (int q = 0; q < 4; q++) {
        int idx = lane + 32 * q, ch0 = 2 * idx;
        float inv = 1.f / (d[q] + 1e-16f);
        float v0 = s0[q] * inv + bias[ch0];
        float v1 = s1[q] * inv + bias[ch0 + 1];
        v0 = v0 > 0.f ? v0 : 0.f;
        v1 = v1 > 0.f ? v1 : 0.f;
        __nv_bfloat16 h0 = __float2bfloat16(v0);
        __nv_bfloat16 h1 = __float2bfloat16(v1);
        __nv_bfloat162 hi; hi.x = h0; hi.y = h1;
        __nv_bfloat162 lo;
        lo.x = __float2bfloat16(v0 - __bfloat162float(h0));
        lo.y = __float2bfloat16(v1 - __bfloat162float(h1));
        *reinterpret_cast<__nv_bfloat162*>(&hp[ch0]) = hi;
        *reinterpret_cast<__nv_bfloat162*>(&hp[D1v + ch0]) = lo;
    }
}

// ---------------- layer-2 aggregation + bias + log_softmax ----------------
__global__ __launch_bounds__(256) void k_agg2(const int* __restrict__ src,
                                              const float* __restrict__ att,
                                              const float* __restrict__ bias,
                                              float* __restrict__ out) {
    int warp = (blockIdx.x * blockDim.x + threadIdx.x) >> 5;
    int lane = threadIdx.x & 31;
    if (warp >= N2v) return;

    bool ok = lane < 24;
    const __half2* xr = reinterpret_cast<const __half2*>(&g_xr2[(size_t)warp * OUTCv]);
    float2 xrr = ok ? __half22float2(xr[lane]) : make_float2(0.f, 0.f);
    float2 attr = ok ? make_float2(att[2 * lane], att[2 * lane + 1]) : make_float2(0.f, 0.f);
    float s0 = 0.f, s1 = 0.f, m = -1e30f, dd = 0.f;

    int a0 = g_off2[warp], c = g_cnt2[warp];
    for (int j = 0; j < c; j++) {
        int sn = src[g_eidx2[a0 + j]];
        const __half2* xlp = reinterpret_cast<const __half2*>(&g_xl2[(size_t)sn * OUTCv]);
        float2 xl = ok ? __half22float2(xlp[lane]) : make_float2(0.f, 0.f);
        float e0 = xl.x + xrr.x; e0 = e0 > 0.f ? e0 : 0.2f * e0;
        float e1 = xl.y + xrr.y; e1 = e1 > 0.f ? e1 : 0.2f * e1;
        float p = ok ? (e0 * attr.x + e1 * attr.y) : 0.f;
#pragma unroll
        for (int o = 16; o; o >>= 1) p += __shfl_xor_sync(0xffffffffu, p, o);
        float mn = fmaxf(m, p);
        float c1 = __expf(m - mn);
        float c2 = __expf(p - mn);
        dd = dd * c1 + c2;
        m = mn;
        s0 = s0 * c1 + c2 * xl.x;
        s1 = s1 * c1 + c2 * xl.y;
    }
    float inv = 1.f / (dd + 1e-16f);
    float v0 = ok ? s0 * inv + bias[2 * lane] : -1e30f;
    float v1 = ok ? s1 * inv + bias[2 * lane + 1] : -1e30f;

    float mx = fmaxf(v0, v1);
#pragma unroll
    for (int o = 16; o; o >>= 1) mx = fmaxf(mx, __shfl_xor_sync(0xffffffffu, mx, o));
    float se = ok ? (__expf(v0 - mx) + __expf(v1 - mx)) : 0.f;
#pragma unroll
    for (int o = 16; o; o >>= 1) se += __shfl_xor_sync(0xffffffffu, se, o);
    float lse = mx + logf(se);
    if (ok) {
        float2 r = make_float2(v0 - lse, v1 - lse);
        *reinterpret_cast<float2*>(&out[(size_t)warp * OUTCv + 2 * lane]) = r;
    }
}

// ---------------- launch ----------------
static inline int cdiv(int a, int b) { return (a + b - 1) / b; }

extern "C" void kernel_launch(void* const* d_in, const int* in_sizes, int n_in,
                              void* d_out, int out_size) {
    const float* x     = (const float*)d_in[0];
    const float* Wl1   = (const float*)d_in[1];
    const float* bl1   = (const float*)d_in[2];
    const float* Wr1   = (const float*)d_in[3];
    const float* br1   = (const float*)d_in[4];
    const float* att1  = (const float*)d_in[5];
    const float* bias1 = (const float*)d_in[6];
    const float* Wl2   = (const float*)d_in[7];
    const float* bl2   = (const float*)d_in[8];
    const float* Wr2   = (const float*)d_in[9];
    const float* br2   = (const float*)d_in[10];
    const float* att2  = (const float*)d_in[11];
    const float* bias2 = (const float*)d_in[12];
    const int*   src1  = (const int*)d_in[13];
    const int*   dst1  = (const int*)d_in[14];
    const int*   src2  = (const int*)d_in[15];
    const int*   dst2  = (const int*)d_in[16];
    float* out = (float*)d_out;

    __nv_bfloat16 *xcat, *B1l, *B1r, *B2l, *B2r, *hcat;
    __half *xl1, *xr1, *xl2, *xr2;
    int *cnt1, *off1, *cnt2, *off2, *part1, *part2;
    cudaGetSymbolAddress((void**)&xcat,  g_xcat);
    cudaGetSymbolAddress((void**)&hcat,  g_hcat);
    cudaGetSymbolAddress((void**)&B1l,   g_B1l);
    cudaGetSymbolAddress((void**)&B1r,   g_B1r);
    cudaGetSymbolAddress((void**)&B2l,   g_B2l);
    cudaGetSymbolAddress((void**)&B2r,   g_B2r);
    cudaGetSymbolAddress((void**)&xl1,   g_xl1);
    cudaGetSymbolAddress((void**)&xr1,   g_xr1);
    cudaGetSymbolAddress((void**)&xl2,   g_xl2);
    cudaGetSymbolAddress((void**)&xr2,   g_xr2);
    cudaGetSymbolAddress((void**)&cnt1,  g_cnt1);
    cudaGetSymbolAddress((void**)&off1,  g_off1);
    cudaGetSymbolAddress((void**)&cnt2,  g_cnt2);
    cudaGetSymbolAddress((void**)&off2,  g_off2);
    cudaGetSymbolAddress((void**)&part1, g_part1);
    cudaGetSymbolAddress((void**)&part2, g_part2);

    const int SMEM1 = 256 * (2 * 128 + 8) * 2 + 2 * 128 * 40 * 2;   // 155648
    const int SMEM2 = 64  * (2 * 256 + 8) * 2 + 2 * 128 * 40 * 2;   // 87040
    cudaFuncSetAttribute(gemm_mma<256, 128>, cudaFuncAttributeMaxDynamicSharedMemorySize, SMEM1);
    cudaFuncSetAttribute(gemm_mma<48, 256>,  cudaFuncAttributeMaxDynamicSharedMemorySize, SMEM2);

    // ---- fused CSR build (both layers) ----
    k_zero_all<<<cdiv(N1v, 256), 256>>>();
    k_count_all<<<cdiv(E1v + E2v, 256), 256>>>(dst1, dst2);
    int nb1 = cdiv(N1v, 1024), nb2 = cdiv(N2v, 1024);
    k_scan_block<<<nb1, 1024>>>(cnt1, off1, part1, N1v);
    k_scan_block<<<nb2, 1024>>>(cnt2, off2, part2, N2v);
    k_scan_part<<<1, 1024>>>(part1, nb1);
    k_scan_part<<<1, 1024>>>(part2, nb2);
    k_scan_add<<<nb1, 1024>>>(off1, part1, N1v);
    k_scan_add<<<nb2, 1024>>>(off2, part2, N2v);
    k_scatter_all<<<cdiv(E1v + E2v, 256), 256>>>(dst1, dst2);
    k_sort_all<<<cdiv(N1v + N2v, 256), 256>>>();

    // ---- splits ----
    k_split<<<cdiv(N0v * INCv, 256), 256>>>(x, xcat, N0v * INCv, INCv);
    k_splitW_all<<<cdiv(2 * (INCv * D1v + D1v * OUTCv), 256), 256>>>(Wl1, Wr1, Wl2, Wr2);

    // ---- layer-1 transforms (HMMA, fp16 out) ----
    gemm_mma<256, 128><<<148, 512, SMEM1>>>(xcat, B1l, bl1, xl1, N0v);
    gemm_mma<256, 128><<<148, 512, SMEM1>>>(xcat, B1r, br1, xr1, N1v);

    // ---- layer-1 softmax-aggregate + relu ----
    k_agg1<<<cdiv(N1v * 32, 256), 256>>>(src1, att1, bias1);

    // ---- layer-2 transforms ----
    gemm_mma<48, 256><<<148, 512, SMEM2>>>(hcat, B2l, bl2, xl2, N1v);
    gemm_mma<48, 256><<<125, 512, SMEM2>>>(hcat, B2r, br2, xr2, N2v);

    // ---- layer-2 softmax-aggregate + bias + log_softmax ----
    k_agg2<<<cdiv(N2v * 32, 256), 256>>>(src2, att2, bias2, out);

    (void)in_sizes; (void)n_in; (void)out_size;
}

// round 11
// speedup vs baseline: 1.9256x; 1.1778x over previous
#include <cuda_runtime.h>
#include <cuda_bf16.h>
#include <cuda_fp16.h>
#include <cstdint>
#include <cstddef>

// ---------------- problem constants ----------------
#define N0v   320000
#define N1v   80000
#define N2v   16000
#define E1v   800000
#define E2v   160000
#define INCv  128
#define HIDv  64
#define H1c   4
#define OUTCv 48
#define D1v   (H1c*HIDv)   // 256
#define NB1   ((N1v + 1023) / 1024)   // 79
#define NB2   ((N2v + 1023) / 1024)   // 16

// ---------------- scratch (device globals) ----------------
__device__ __nv_bfloat16 g_xcat[(size_t)N0v * 2 * INCv];   // x split hi|lo
__device__ __half g_xl1[(size_t)N0v * D1v];                // fp16 x@Wl1+bl1
__device__ __half g_xr1[(size_t)N1v * D1v];
__device__ __nv_bfloat16 g_hcat[(size_t)N1v * 2 * D1v];    // relu(h) split
__device__ __half g_xl2[(size_t)N1v * OUTCv];
__device__ __half g_xr2[(size_t)N2v * OUTCv];
__device__ __nv_bfloat16 g_B1l[(size_t)D1v * 2 * INCv];    // Wl1^T split [256][256]
__device__ __nv_bfloat16 g_B1r[(size_t)D1v * 2 * INCv];
__device__ __nv_bfloat16 g_B2l[(size_t)OUTCv * 2 * D1v];   // Wl2^T split [48][512]
__device__ __nv_bfloat16 g_B2r[(size_t)OUTCv * 2 * D1v];

__device__ int g_cnt1[N1v], g_off1[N1v], g_cur1[N1v];
__device__ int g_cnt2[N2v], g_off2[N2v], g_cur2[N2v];
__device__ int g_eidx1[E1v], g_eidx2[E2v];
__device__ int g_part1[256], g_part2[256];

// ---------------- PTX helpers ----------------
__device__ __forceinline__ uint32_t smem_u32(const void* p) {
    uint32_t a;
    asm("{ .reg .u64 t; cvta.to.shared.u64 t, %1; cvt.u32.u64 %0, t; }" : "=r"(a) : "l"(p));
    return a;
}
__device__ __forceinline__ void ldmatrix_x4(uint32_t* r, uint32_t addr) {
    asm volatile("ldmatrix.sync.aligned.m8n8.x4.shared.b16 {%0,%1,%2,%3}, [%4];"
                 : "=r"(r[0]), "=r"(r[1]), "=r"(r[2]), "=r"(r[3]) : "r"(addr));
}
__device__ __forceinline__ void mma_bf16(float* c, const uint32_t* a, uint32_t b0, uint32_t b1) {
    asm volatile("mma.sync.aligned.m16n8k16.row.col.f32.bf16.bf16.f32 "
                 "{%0,%1,%2,%3}, {%4,%5,%6,%7}, {%8,%9}, {%0,%1,%2,%3};"
                 : "+f"(c[0]), "+f"(c[1]), "+f"(c[2]), "+f"(c[3])
                 : "r"(a[0]), "r"(a[1]), "r"(a[2]), "r"(a[3]), "r"(b0), "r"(b1));
}
__device__ __forceinline__ void cp_async16(uint32_t saddr, const void* gptr) {
    asm volatile("cp.async.cg.shared.global [%0], [%1], 16;" :: "r"(saddr), "l"(gptr));
}
#define CP_COMMIT() asm volatile("cp.async.commit_group;" ::: "memory")
#define CP_WAIT(n)  asm volatile("cp.async.wait_group %0;" :: "n"(n) : "memory")

// ---------------- bf16 split conversions ----------------
__global__ void k_split(const float* __restrict__ in, __nv_bfloat16* __restrict__ out,
                        int n, int K) {
    int i = blockIdx.x * blockDim.x + threadIdx.x;
    if (i >= n) return;
    int r = i / K, c = i % K;
    float v = in[i];
    __nv_bfloat16 h = __float2bfloat16(v);
    __nv_bfloat16 l = __float2bfloat16(v - __bfloat162float(h));
    out[(size_t)r * 2 * K + c] = h;
    out[(size_t)r * 2 * K + K + c] = l;
}
__global__ void k_splitW_all(const float* __restrict__ Wl1, const float* __restrict__ Wr1,
                             const float* __restrict__ Wl2, const float* __restrict__ Wr2) {
    const int S1 = INCv * D1v;     // 32768
    const int S2 = D1v * OUTCv;    // 12288
    int i = blockIdx.x * blockDim.x + threadIdx.x;
    const float* W; __nv_bfloat16* out; int K, N, j;
    if (i < S1)               { W = Wl1; out = g_B1l; K = INCv; N = D1v;  j = i; }
    else if (i < 2 * S1)      { W = Wr1; out = g_B1r; K = INCv; N = D1v;  j = i - S1; }
    else if (i < 2 * S1 + S2) { W = Wl2; out = g_B2l; K = D1v;  N = OUTCv; j = i - 2 * S1; }
    else if (i < 2 * (S1 + S2)) { W = Wr2; out = g_B2r; K = D1v; N = OUTCv; j = i - 2 * S1 - S2; }
    else return;
    int k = j / N, n = j % N;
    float v = W[j];
    __nv_bfloat16 h = __float2bfloat16(v);
    __nv_bfloat16 l = __float2bfloat16(v - __bfloat162float(h));
    out[(size_t)n * 2 * K + k] = h;
    out[(size_t)n * 2 * K + K + k] = l;
}

// ---------------- HMMA GEMM: C[M,N_] = Acat@Bcat^T + bias (fp16 out) ----------------
template <int N_, int K_>
__global__ __launch_bounds__(512) void gemm_mma(const __nv_bfloat16* __restrict__ Acat,
                                                const __nv_bfloat16* __restrict__ Bcat,
                                                const float* __restrict__ bias,
                                                __half* __restrict__ C, int M) {
    constexpr int NB  = (N_ + 63) & ~63;
    constexpr int KC2 = 2 * K_;
    constexpr int LDB = KC2 + 8;
    constexpr int LDA = 40;
    constexpr int KP  = K_ / 32;
    constexpr int CH  = 3 * KP;
    constexpr int WN  = NB / 4;
    constexpr int NT  = WN / 8;
    constexpr int NPAIR = NT / 2;

    extern __shared__ char smem[];
    __nv_bfloat16* Bs = reinterpret_cast<__nv_bfloat16*>(smem);
    const uint32_t sBs = smem_u32(smem);
    const uint32_t sAs = sBs + NB * LDB * 2;

    const int tid = threadIdx.x, lid = tid & 31, wid = tid >> 5;
    const int wm = wid >> 2, wn = wid & 3;

    for (int i = tid; i < NB * (KC2 / 8); i += 512) {
        int row = i / (KC2 / 8), v = (i % (KC2 / 8)) * 8;
        uint4 val = make_uint4(0u, 0u, 0u, 0u);
        if (row < N_) val = *reinterpret_cast<const uint4*>(&Bcat[(size_t)row * KC2 + v]);
        *reinterpret_cast<uint4*>(&Bs[row * LDB + v]) = val;
    }
    __syncthreads();

    const int nTiles = M / 128;
    for (int t = blockIdx.x; t < nTiles; t += gridDim.x) {
        const size_t m0 = (size_t)t * 128;
        float acc[2][NT][4];
#pragma unroll
        for (int i = 0; i < 2; i++)
#pragma unroll
            for (int j = 0; j < NT; j++)
#pragma unroll
                for (int q = 0; q < 4; q++) acc[i][j][q] = 0.f;

        {
            int row = tid >> 2, v = (tid & 3) * 8;
            cp_async16(sAs + 2 * (row * LDA + v), &Acat[(m0 + row) * KC2 + v]);
            CP_COMMIT();
        }

        for (int c = 0; c < CH; c++) {
            if (c + 1 < CH) {
                const int cn = c + 1;
                const int p = cn / KP, kk = (cn % KP) * 32;
                const int ak = (p == 2 ? K_ : 0) + kk;
                const int st = cn & 1;
                int row = tid >> 2, v = (tid & 3) * 8;
                cp_async16(sAs + 2 * (st * 128 * LDA + row * LDA + v),
                           &Acat[(m0 + row) * KC2 + ak + v]);
                CP_COMMIT();
                CP_WAIT(1);
            } else {
                CP_WAIT(0);
            }
            __syncthreads();

            const int p  = c / KP, kk = (c % KP) * 32;
            const int bk = (p == 1 ? K_ : 0) + kk;
            const int stageOff = (c & 1) * 128 * LDA;
#pragma unroll
            for (int kt = 0; kt < 2; kt++) {
                uint32_t a[2][4];
#pragma unroll
                for (int mt = 0; mt < 2; mt++) {
                    uint32_t addr = sAs + 2 * (stageOff +
                        (wm * 32 + mt * 16 + (lid & 15)) * LDA + kt * 16 + (lid >> 4) * 8);
                    ldmatrix_x4(a[mt], addr);
                }
#pragma unroll
                for (int np = 0; np < NPAIR; np++) {
                    uint32_t b[4];
                    int g = lid >> 3;
                    int nrow = wn * WN + np * 16 + ((g >> 1) << 3) + (lid & 7);
                    int col  = bk + kt * 16 + ((g & 1) << 3);
                    ldmatrix_x4(b, sBs + 2 * (nrow * LDB + col));
                    mma_bf16(acc[0][np * 2 + 0], a[0], b[0], b[1]);
                    mma_bf16(acc[0][np * 2 + 1], a[0], b[2], b[3]);
                    mma_bf16(acc[1][np * 2 + 0], a[1], b[0], b[1]);
                    mma_bf16(acc[1][np * 2 + 1], a[1], b[2], b[3]);
                }
            }
            __syncthreads();
        }

#pragma unroll
        for (int mt = 0; mt < 2; mt++) {
#pragma unroll
            for (int nt = 0; nt < NT; nt++) {
                int colb = wn * WN + nt * 8 + (lid & 3) * 2;
                if (colb < N_) {
                    size_t r0 = m0 + wm * 32 + mt * 16 + (lid >> 2);
                    float b0 = bias[colb], b1 = bias[colb + 1];
                    __half2 v0 = __floats2half2_rn(acc[mt][nt][0] + b0, acc[mt][nt][1] + b1);
                    __half2 v1 = __floats2half2_rn(acc[mt][nt][2] + b0, acc[mt][nt][3] + b1);
                    *reinterpret_cast<__half2*>(&C[r0 * N_ + colb]) = v0;
                    *reinterpret_cast<__half2*>(&C[(r0 + 8) * N_ + colb]) = v1;
                }
            }
        }
        __syncthreads();
    }
}

// ---------------- fused CSR build ----------------
__global__ void k_zero_all() {
    int i = blockIdx.x * blockDim.x + threadIdx.x;
    if (i < N1v) { g_cnt1[i] = 0; g_cur1[i] = 0; }
    if (i < N2v) { g_cnt2[i] = 0; g_cur2[i] = 0; }
}
__global__ void k_count_all(const int* __restrict__ dst1, const int* __restrict__ dst2) {
    int i = blockIdx.x * blockDim.x + threadIdx.x;
    if (i < E1v) atomicAdd(&g_cnt1[dst1[i]], 1);
    else if (i < E1v + E2v) atomicAdd(&g_cnt2[dst2[i - E1v]], 1);
}
// one launch: blocks [0,NB1) scan cnt1, blocks [NB1,NB1+NB2) scan cnt2
__global__ __launch_bounds__(1024) void k_scanb_all() {
    int b = blockIdx.x;
    const int* in; int* outp; int* part; int n; int lb;
    if (b < NB1) { in = g_cnt1; outp = g_off1; part = g_part1; n = N1v; lb = b; }
    else         { in = g_cnt2; outp = g_off2; part = g_part2; n = N2v; lb = b - NB1; }
    __shared__ int sh[1024];
    int t = threadIdx.x, i = lb * 1024 + t;
    int v = (i < n) ? in[i] : 0;
    sh[t] = v;
    __syncthreads();
    for (int d = 1; d < 1024; d <<= 1) {
        int add = (t >= d) ? sh[t - d] : 0;
        __syncthreads();
        sh[t] += add;
        __syncthreads();
    }
    if (i < n) outp[i] = sh[t] - v;
    if (t == 1023) part[lb] = sh[1023];
}
__global__ __launch_bounds__(128) void k_scanp_all() {
    int* part = blockIdx.x ? g_part2 : g_part1;
    int nb = blockIdx.x ? NB2 : NB1;
    __shared__ int sh[128];
    int t = threadIdx.x;
    int v = (t < nb) ? part[t] : 0;
    sh[t] = v;
    __syncthreads();
    for (int d = 1; d < 128; d <<= 1) {
        int add = (t >= d) ? sh[t - d] : 0;
        __syncthreads();
        sh[t] += add;
        __syncthreads();
    }
    if (t < nb) part[t] = sh[t] - v;
}
__global__ __launch_bounds__(1024) void k_scana_all() {
    int b = blockIdx.x;
    if (b < NB1) {
        int i = b * 1024 + threadIdx.x;
        if (i < N1v) g_off1[i] += g_part1[b];
    } else {
        int i = (b - NB1) * 1024 + threadIdx.x;
        if (i < N2v) g_off2[i] += g_part2[b - NB1];
    }
}
__global__ void k_scatter_all(const int* __restrict__ dst1, const int* __restrict__ dst2) {
    int i = blockIdx.x * blockDim.x + threadIdx.x;
    if (i < E1v) {
        int d = dst1[i];
        g_eidx1[g_off1[d] + atomicAdd(&g_cur1[d], 1)] = i;
    } else if (i < E1v + E2v) {
        int e = i - E1v;
        int d = dst2[e];
        g_eidx2[g_off2[d] + atomicAdd(&g_cur2[d], 1)] = e;
    }
}
__global__ void k_sort_all() {
    int i = blockIdx.x * blockDim.x + threadIdx.x;
    int a, c; int* eidx;
    if (i < N1v) { a = g_off1[i]; c = g_cnt1[i]; eidx = g_eidx1; }
    else if (i < N1v + N2v) { int j = i - N1v; a = g_off2[j]; c = g_cnt2[j]; eidx = g_eidx2; }
    else return;
    for (int x = 1; x < c; x++) {
        int key = eidx[a + x];
        int y = x - 1;
        while (y >= 0 && eidx[a + y] > key) { eidx[a + y + 1] = eidx[a + y]; y--; }
        eidx[a + y + 1] = key;
    }
}

// ---------------- layer-1 aggregation (fp16 gather, depth-2 prefetch, online softmax) ----------------
__global__ __launch_bounds__(256) void k_agg1(const int* __restrict__ src,
                                              const float* __restrict__ att,
                                              const float* __restrict__ bias) {
    int warp = (blockIdx.x * blockDim.x + threadIdx.x) >> 5;
    int lane = threadIdx.x & 31;
    if (warp >= N1v) return;

    const __half2* xr = reinterpret_cast<const __half2*>(&g_xr1[(size_t)warp * D1v]);
    float2 xrr[4], attr[4];
    float s0[4], s1[4], m[4], d[4];
#pragma unroll
    for (int q = 0; q < 4; q++) {
        int idx = lane + 32 * q;
        xrr[q] = __half22float2(xr[idx]);
        attr[q] = make_float2(att[2 * idx], att[2 * idx + 1]);
        s0[q] = 0.f; s1[q] = 0.f; m[q] = -1e30f; d[q] = 0.f;
    }

    int a0 = g_off1[warp], c = g_cnt1[warp];
    uint32_t xb[4];
    int sn_next = 0;
    if (c > 0) {
        int s0n = src[g_eidx1[a0]];
        const uint32_t* p = reinterpret_cast<const uint32_t*>(&g_xl1[(size_t)s0n * D1v]);
#pragma unroll
        for (int q = 0; q < 4; q++) xb[q] = p[lane + 32 * q];
        if (c > 1) sn_next = src[g_eidx1[a0 + 1]];
    }

    for (int j = 0; j < c; j++) {
        float2 xl[4];
#pragma unroll
        for (int q = 0; q < 4; q++)
            xl[q] = __half22float2(*reinterpret_cast<const __half2*>(&xb[q]));
        // prefetch row j+1 and src index j+2 (overlap with compute below)
        if (j + 1 < c) {
            const uint32_t* p = reinterpret_cast<const uint32_t*>(&g_xl1[(size_t)sn_next * D1v]);
#pragma unroll
            for (int q = 0; q < 4; q++) xb[q] = p[lane + 32 * q];
            if (j + 2 < c) sn_next = src[g_eidx1[a0 + j + 2]];
        }
        float p4[4];
#pragma unroll
        for (int q = 0; q < 4; q++) {
            float e0 = xl[q].x + xrr[q].x; e0 = e0 > 0.f ? e0 : 0.2f * e0;
            float e1 = xl[q].y + xrr[q].y; e1 = e1 > 0.f ? e1 : 0.2f * e1;
            p4[q] = e0 * attr[q].x + e1 * attr[q].y;
        }
        // grouped reduction: 8 + 3 + 4 shuffles
#pragma unroll
        for (int q = 0; q < 4; q++) p4[q] += __shfl_xor_sync(0xffffffffu, p4[q], 16);
#pragma unroll
        for (int q = 0; q < 4; q++) p4[q] += __shfl_xor_sync(0xffffffffu, p4[q], 8);
        int g = lane >> 3;
        float v = (g == 0) ? p4[0] : (g == 1) ? p4[1] : (g == 2) ? p4[2] : p4[3];
        v += __shfl_xor_sync(0xffffffffu, v, 4);
        v += __shfl_xor_sync(0xffffffffu, v, 2);
        v += __shfl_xor_sync(0xffffffffu, v, 1);
#pragma unroll
        for (int q = 0; q < 4; q++) {
            float hq = __shfl_sync(0xffffffffu, v, q << 3);
            float mn = fmaxf(m[q], hq);
            float c1 = __expf(m[q] - mn);
            float c2 = __expf(hq - mn);
            d[q] = d[q] * c1 + c2;
            m[q] = mn;
            s0[q] = s0[q] * c1 + c2 * xl[q].x;
            s1[q] = s1[q] * c1 + c2 * xl[q].y;
        }
    }
    __nv_bfloat16* hp = &g_hcat[(size_t)warp * 2 * D1v];
#pragma unroll
    for (int q = 0; q < 4; q++) {
        int idx = lane + 32 * q, ch0 = 2 * idx;
        float inv = 1.f / (d[q] + 1e-16f);
        float v0 = s0[q] * inv + bias[ch0];
        float v1 = s1[q] * inv + bias[ch0 + 1];
        v0 = v0 > 0.f ? v0 : 0.f;
        v1 = v1 > 0.f ? v1 : 0.f;
        __nv_bfloat16 h0 = __float2bfloat16(v0);
        __nv_bfloat16 h1 = __float2bfloat16(v1);
        __nv_bfloat162 hi; hi.x = h0; hi.y = h1;
        __nv_bfloat162 lo;
        lo.x = __float2bfloat16(v0 - __bfloat162float(h0));
        lo.y = __float2bfloat16(v1 - __bfloat162float(h1));
        *reinterpret_cast<__nv_bfloat162*>(&hp[ch0]) = hi;
        *reinterpret_cast<__nv_bfloat162*>(&hp[D1v + ch0]) = lo;
    }
}

// ---------------- layer-2 aggregation + bias + log_softmax ----------------
__global__ __launch_bounds__(256) void k_agg2(const int* __restrict__ src,
                                              const float* __restrict__ att,
                                              const float* __restrict__ bias,
                                              float* __restrict__ out) {
    int warp = (blockIdx.x * blockDim.x + threadIdx.x) >> 5;
    int lane = threadIdx.x & 31;
    if (warp >= N2v) return;

    bool ok = lane < 24;
    const __half2* xr = reinterpret_cast<const __half2*>(&g_xr2[(size_t)warp * OUTCv]);
    float2 xrr = ok ? __half22float2(xr[lane]) : make_float2(0.f, 0.f);
    float2 attr = ok ? make_float2(att[2 * lane], att[2 * lane + 1]) : make_float2(0.f, 0.f);
    float s0 = 0.f, s1 = 0.f, m = -1e30f, dd = 0.f;

    int a0 = g_off2[warp], c = g_cnt2[warp];
    uint32_t xb = 0;
    int sn_next = 0;
    if (c > 0) {
        int s0n = src[g_eidx2[a0]];
        if (ok) xb = reinterpret_cast<const uint32_t*>(&g_xl2[(size_t)s0n * OUTCv])[lane];
        if (c > 1) sn_next = src[g_eidx2[a0 + 1]];
    }

    for (int j = 0; j < c; j++) {
        float2 xl = __half22float2(*reinterpret_cast<const __half2*>(&xb));
        if (j + 1 < c) {
            if (ok) xb = reinterpret_cast<const uint32_t*>(&g_xl2[(size_t)sn_next * OUTCv])[lane];
            if (j + 2 < c) sn_next = src[g_eidx2[a0 + j + 2]];
        }
        float e0 = xl.x + xrr.x; e0 = e0 > 0.f ? e0 : 0.2f * e0;
        float e1 = xl.y + xrr.y; e1 = e1 > 0.f ? e1 : 0.2f * e1;
        float p = ok ? (e0 * attr.x + e1 * attr.y) : 0.f;
#pragma unroll
        for (int o = 16; o; o >>= 1) p += __shfl_xor_sync(0xffffffffu, p, o);
        float mn = fmaxf(m, p);
        float c1 = __expf(m - mn);
        float c2 = __expf(p - mn);
        dd = dd * c1 + c2;
        m = mn;
        s0 = s0 * c1 + c2 * xl.x;
        s1 = s1 * c1 + c2 * xl.y;
    }
    float inv = 1.f / (dd + 1e-16f);
    float v0 = ok ? s0 * inv + bias[2 * lane] : -1e30f;
    float v1 = ok ? s1 * inv + bias[2 * lane + 1] : -1e30f;

    float mx = fmaxf(v0, v1);
#pragma unroll
    for (int o = 16; o; o >>= 1) mx = fmaxf(mx, __shfl_xor_sync(0xffffffffu, mx, o));
    float se = ok ? (__expf(v0 - mx) + __expf(v1 - mx)) : 0.f;
#pragma unroll
    for (int o = 16; o; o >>= 1) se += __shfl_xor_sync(0xffffffffu, se, o);
    float lse = mx + logf(se);
    if (ok) {
        float2 r = make_float2(v0 - lse, v1 - lse);
        *reinterpret_cast<float2*>(&out[(size_t)warp * OUTCv + 2 * lane]) = r;
    }
}

// ---------------- launch ----------------
static inline int cdiv(int a, int b) { return (a + b - 1) / b; }

extern "C" void kernel_launch(void* const* d_in, const int* in_sizes, int n_in,
                              void* d_out, int out_size) {
    const float* x     = (const float*)d_in[0];
    const float* Wl1   = (const float*)d_in[1];
    const float* bl1   = (const float*)d_in[2];
    const float* Wr1   = (const float*)d_in[3];
    const float* br1   = (const float*)d_in[4];
    const float* att1  = (const float*)d_in[5];
    const float* bias1 = (const float*)d_in[6];
    const float* Wl2   = (const float*)d_in[7];
    const float* bl2   = (const float*)d_in[8];
    const float* Wr2   = (const float*)d_in[9];
    const float* br2   = (const float*)d_in[10];
    const float* att2  = (const float*)d_in[11];
    const float* bias2 = (const float*)d_in[12];
    const int*   src1  = (const int*)d_in[13];
    const int*   dst1  = (const int*)d_in[14];
    const int*   src2  = (const int*)d_in[15];
    const int*   dst2  = (const int*)d_in[16];
    float* out = (float*)d_out;

    __nv_bfloat16 *xcat, *B1l, *B1r, *B2l, *B2r, *hcat;
    __half *xl1, *xr1, *xl2, *xr2;
    cudaGetSymbolAddress((void**)&xcat,  g_xcat);
    cudaGetSymbolAddress((void**)&hcat,  g_hcat);
    cudaGetSymbolAddress((void**)&B1l,   g_B1l);
    cudaGetSymbolAddress((void**)&B1r,   g_B1r);
    cudaGetSymbolAddress((void**)&B2l,   g_B2l);
    cudaGetSymbolAddress((void**)&B2r,   g_B2r);
    cudaGetSymbolAddress((void**)&xl1,   g_xl1);
    cudaGetSymbolAddress((void**)&xr1,   g_xr1);
    cudaGetSymbolAddress((void**)&xl2,   g_xl2);
    cudaGetSymbolAddress((void**)&xr2,   g_xr2);

    const int SMEM1 = 256 * (2 * 128 + 8) * 2 + 2 * 128 * 40 * 2;   // 155648
    const int SMEM2 = 64  * (2 * 256 + 8) * 2 + 2 * 128 * 40 * 2;   // 87040
    cudaFuncSetAttribute(gemm_mma<256, 128>, cudaFuncAttributeMaxDynamicSharedMemorySize, SMEM1);
    cudaFuncSetAttribute(gemm_mma<48, 256>,  cudaFuncAttributeMaxDynamicSharedMemorySize, SMEM2);

    // ---- splits + layer-1 GEMMs first (no CSR dependency); launch #4 = big GEMM -> ncu ----
    k_split<<<cdiv(N0v * INCv, 256), 256>>>(x, xcat, N0v * INCv, INCv);                       // 1
    k_splitW_all<<<cdiv(2 * (INCv * D1v + D1v * OUTCv), 256), 256>>>(Wl1, Wr1, Wl2, Wr2);     // 2
    gemm_mma<256, 128><<<148, 512, SMEM1>>>(xcat, B1r, br1, xr1, N1v);                        // 3
    gemm_mma<256, 128><<<148, 512, SMEM1>>>(xcat, B1l, bl1, xl1, N0v);                        // 4 (profiled)

    // ---- fused CSR build (both layers) ----
    k_zero_all<<<cdiv(N1v, 256), 256>>>();                                                    // 5
    k_count_all<<<cdiv(E1v + E2v, 256), 256>>>(dst1, dst2);                                   // 6
    k_scanb_all<<<NB1 + NB2, 1024>>>();                                                       // 7
    k_scanp_all<<<2, 128>>>();                                                                // 8
    k_scana_all<<<NB1 + NB2, 1024>>>();                                                       // 9
    k_scatter_all<<<cdiv(E1v + E2v, 256), 256>>>(dst1, dst2);                                 // 10
    k_sort_all<<<cdiv(N1v + N2v, 256), 256>>>();                                              // 11

    // ---- layer-1 softmax-aggregate + relu ----
    k_agg1<<<cdiv(N1v * 32, 256), 256>>>(src1, att1, bias1);                                  // 12

    // ---- layer-2 transforms ----
    gemm_mma<48, 256><<<148, 512, SMEM2>>>(hcat, B2l, bl2, xl2, N1v);                         // 13
    gemm_mma<48, 256><<<125, 512, SMEM2>>>(hcat, B2r, br2, xr2, N2v);                         // 14

    // ---- layer-2 softmax-aggregate + bias + log_softmax ----
    k_agg2<<<cdiv(N2v * 32, 256), 256>>>(src2, att2, bias2, out);                             // 15

    (void)in_sizes; (void)n_in; (void)out_size;
}

// round 15
// speedup vs baseline: 2.8474x; 1.4787x over previous
#include <cuda_runtime.h>
#include <cuda_bf16.h>
#include <cuda_fp16.h>
#include <cstdint>
#include <cstddef>

// ---------------- problem constants ----------------
#define N0v   320000
#define N1v   80000
#define N2v   16000
#define E1v   800000
#define E2v   160000
#define INCv  128
#define HIDv  64
#define H1c   4
#define OUTCv 48
#define D1v   (H1c*HIDv)   // 256
#define NB1   ((N1v + 1023) / 1024)   // 79
#define NB2   ((N2v + 1023) / 1024)   // 16

// ---------------- scratch (device globals) ----------------
__device__ __nv_bfloat16 g_xb[(size_t)N0v * INCv];        // bf16(x)
__device__ __half g_xl1[(size_t)N0v * D1v];               // fp16 x@Wl1+bl1
__device__ __half g_xr1[(size_t)N1v * D1v];
__device__ __nv_bfloat16 g_h[(size_t)N1v * D1v];          // bf16 relu(h)
__device__ __half g_xl2[(size_t)N1v * OUTCv];
__device__ __half g_xr2[(size_t)N2v * OUTCv];
__device__ __nv_bfloat16 g_B1l[(size_t)D1v * INCv];       // Wl1^T bf16 [256][128]
__device__ __nv_bfloat16 g_B1r[(size_t)D1v * INCv];
__device__ __nv_bfloat16 g_B2l[(size_t)OUTCv * D1v];      // Wl2^T bf16 [48][256]
__device__ __nv_bfloat16 g_B2r[(size_t)OUTCv * D1v];

__device__ int g_cnt1[N1v], g_off1[N1v], g_cur1[N1v];
__device__ int g_cnt2[N2v], g_off2[N2v], g_cur2[N2v];
__device__ int g_eidx1[E1v], g_eidx2[E2v];
__device__ int g_part1[256], g_part2[256];

// ---------------- PTX helpers ----------------
__device__ __forceinline__ uint32_t smem_u32(const void* p) {
    uint32_t a;
    asm("{ .reg .u64 t; cvta.to.shared.u64 t, %1; cvt.u32.u64 %0, t; }" : "=r"(a) : "l"(p));
    return a;
}
__device__ __forceinline__ void ldmatrix_x4(uint32_t* r, uint32_t addr) {
    asm volatile("ldmatrix.sync.aligned.m8n8.x4.shared.b16 {%0,%1,%2,%3}, [%4];"
                 : "=r"(r[0]), "=r"(r[1]), "=r"(r[2]), "=r"(r[3]) : "r"(addr));
}
__device__ __forceinline__ void mma_bf16(float* c, const uint32_t* a, uint32_t b0, uint32_t b1) {
    asm volatile("mma.sync.aligned.m16n8k16.row.col.f32.bf16.bf16.f32 "
                 "{%0,%1,%2,%3}, {%4,%5,%6,%7}, {%8,%9}, {%0,%1,%2,%3};"
                 : "+f"(c[0]), "+f"(c[1]), "+f"(c[2]), "+f"(c[3])
                 : "r"(a[0]), "r"(a[1]), "r"(a[2]), "r"(a[3]), "r"(b0), "r"(b1));
}
__device__ __forceinline__ void cp_async16(uint32_t saddr, const void* gptr) {
    asm volatile("cp.async.cg.shared.global [%0], [%1], 16;" :: "r"(saddr), "l"(gptr));
}
#define CP_COMMIT() asm volatile("cp.async.commit_group;" ::: "memory")
#define CP_WAIT(n)  asm volatile("cp.async.wait_group %0;" :: "n"(n) : "memory")

// ---------------- conversions ----------------
// fp32 -> bf16 (vectorized, 4 elems/thread)
__global__ void k_cvt(const float* __restrict__ in, __nv_bfloat16* __restrict__ out, int n4) {
    int i = blockIdx.x * blockDim.x + threadIdx.x;
    if (i >= n4) return;
    float4 v = reinterpret_cast<const float4*>(in)[i];
    __nv_bfloat162 a; a.x = __float2bfloat16(v.x); a.y = __float2bfloat16(v.y);
    __nv_bfloat162 b; b.x = __float2bfloat16(v.z); b.y = __float2bfloat16(v.w);
    uint2 pk;
    pk.x = *reinterpret_cast<uint32_t*>(&a);
    pk.y = *reinterpret_cast<uint32_t*>(&b);
    reinterpret_cast<uint2*>(out)[i] = pk;
}
// transposed weight converts: W[K,N] fp32 -> B[N][K] bf16 (all four)
__global__ void k_cvtW_all(const float* __restrict__ Wl1, const float* __restrict__ Wr1,
                           const float* __restrict__ Wl2, const float* __restrict__ Wr2) {
    const int S1 = INCv * D1v;     // 32768
    const int S2 = D1v * OUTCv;    // 12288
    int i = blockIdx.x * blockDim.x + threadIdx.x;
    const float* W; __nv_bfloat16* out; int N, j;
    if (i < S1)                 { W = Wl1; out = g_B1l; N = D1v;   j = i; }
    else if (i < 2 * S1)        { W = Wr1; out = g_B1r; N = D1v;   j = i - S1; }
    else if (i < 2 * S1 + S2)   { W = Wl2; out = g_B2l; N = OUTCv; j = i - 2 * S1; }
    else if (i < 2 * (S1 + S2)) { W = Wr2; out = g_B2r; N = OUTCv; j = i - 2 * S1 - S2; }
    else return;
    int k = j / N, n = j % N;
    int K = (N == D1v) ? INCv : D1v;
    out[(size_t)n * K + k] = __float2bfloat16(W[j]);
}

// ---------------- HMMA GEMM (single-pass bf16): C[M,N_] = A@B^T + bias, fp16 out ----------------
template <int N_, int K_>
__global__ __launch_bounds__(512) void gemm_mma(const __nv_bfloat16* __restrict__ A,
                                                const __nv_bfloat16* __restrict__ Bcat,
                                                const float* __restrict__ bias,
                                                __half* __restrict__ C, int M) {
    constexpr int NB  = (N_ + 63) & ~63;
    constexpr int LDB = K_ + 8;
    constexpr int LDA = 40;                  // 32 + 8 pad
    constexpr int CH  = K_ / 32;
    constexpr int WN  = NB / 4;
    constexpr int NT  = WN / 8;
    constexpr int NPAIR = NT / 2;

    extern __shared__ char smem[];
    __nv_bfloat16* Bs = reinterpret_cast<__nv_bfloat16*>(smem);
    const uint32_t sBs = smem_u32(smem);
    const uint32_t sAs = sBs + NB * LDB * 2;

    const int tid = threadIdx.x, lid = tid & 31, wid = tid >> 5;
    const int wm = wid >> 2, wn = wid & 3;

    // stationary B
    for (int i = tid; i < NB * (K_ / 8); i += 512) {
        int row = i / (K_ / 8), v = (i % (K_ / 8)) * 8;
        uint4 val = make_uint4(0u, 0u, 0u, 0u);
        if (row < N_) val = *reinterpret_cast<const uint4*>(&Bcat[(size_t)row * K_ + v]);
        *reinterpret_cast<uint4*>(&Bs[row * LDB + v]) = val;
    }
    __syncthreads();

    const int nTiles = M / 128;
    for (int t = blockIdx.x; t < nTiles; t += gridDim.x) {
        const size_t m0 = (size_t)t * 128;
        float acc[2][NT][4];
#pragma unroll
        for (int i = 0; i < 2; i++)
#pragma unroll
            for (int j = 0; j < NT; j++)
#pragma unroll
                for (int q = 0; q < 4; q++) acc[i][j][q] = 0.f;

        {
            int row = tid >> 2, v = (tid & 3) * 8;
            cp_async16(sAs + 2 * (row * LDA + v), &A[(m0 + row) * K_ + v]);
            CP_COMMIT();
        }

        for (int c = 0; c < CH; c++) {
            if (c + 1 < CH) {
                const int ak = (c + 1) * 32;
                const int st = (c + 1) & 1;
                int row = tid >> 2, v = (tid & 3) * 8;
                cp_async16(sAs + 2 * (st * 128 * LDA + row * LDA + v),
                           &A[(m0 + row) * K_ + ak + v]);
                CP_COMMIT();
                CP_WAIT(1);
            } else {
                CP_WAIT(0);
            }
            __syncthreads();

            const int bk = c * 32;
            const int stageOff = (c & 1) * 128 * LDA;
#pragma unroll
            for (int kt = 0; kt < 2; kt++) {
                uint32_t a[2][4];
#pragma unroll
                for (int mt = 0; mt < 2; mt++) {
                    uint32_t addr = sAs + 2 * (stageOff +
                        (wm * 32 + mt * 16 + (lid & 15)) * LDA + kt * 16 + (lid >> 4) * 8);
                    ldmatrix_x4(a[mt], addr);
                }
#pragma unroll
                for (int np = 0; np < NPAIR; np++) {
                    uint32_t b[4];
                    int g = lid >> 3;
                    int nrow = wn * WN + np * 16 + ((g >> 1) << 3) + (lid & 7);
                    int col  = bk + kt * 16 + ((g & 1) << 3);
                    ldmatrix_x4(b, sBs + 2 * (nrow * LDB + col));
                    mma_bf16(acc[0][np * 2 + 0], a[0], b[0], b[1]);
                    mma_bf16(acc[0][np * 2 + 1], a[0], b[2], b[3]);
                    mma_bf16(acc[1][np * 2 + 0], a[1], b[0], b[1]);
                    mma_bf16(acc[1][np * 2 + 1], a[1], b[2], b[3]);
                }
            }
            __syncthreads();
        }

#pragma unroll
        for (int mt = 0; mt < 2; mt++) {
#pragma unroll
            for (int nt = 0; nt < NT; nt++) {
                int colb = wn * WN + nt * 8 + (lid & 3) * 2;
                if (colb < N_) {
                    size_t r0 = m0 + wm * 32 + mt * 16 + (lid >> 2);
                    float b0 = bias[colb], b1 = bias[colb + 1];
                    __half2 v0 = __floats2half2_rn(acc[mt][nt][0] + b0, acc[mt][nt][1] + b1);
                    __half2 v1 = __floats2half2_rn(acc[mt][nt][2] + b0, acc[mt][nt][3] + b1);
                    *reinterpret_cast<__half2*>(&C[r0 * N_ + colb]) = v0;
                    *reinterpret_cast<__half2*>(&C[(r0 + 8) * N_ + colb]) = v1;
                }
            }
        }
        __syncthreads();
    }
}

// ---------------- fused CSR build ----------------
__global__ void k_zero_all() {
    int i = blockIdx.x * blockDim.x + threadIdx.x;
    if (i < N1v) { g_cnt1[i] = 0; g_cur1[i] = 0; }
    if (i < N2v) { g_cnt2[i] = 0; g_cur2[i] = 0; }
}
__global__ void k_count_all(const int* __restrict__ dst1, const int* __restrict__ dst2) {
    int i = blockIdx.x * blockDim.x + threadIdx.x;
    if (i < E1v) atomicAdd(&g_cnt1[dst1[i]], 1);
    else if (i < E1v + E2v) atomicAdd(&g_cnt2[dst2[i - E1v]], 1);
}
__global__ __launch_bounds__(1024) void k_scanb_all() {
    int b = blockIdx.x;
    const int* in; int* outp; int* part; int n; int lb;
    if (b < NB1) { in = g_cnt1; outp = g_off1; part = g_part1; n = N1v; lb = b; }
    else         { in = g_cnt2; outp = g_off2; part = g_part2; n = N2v; lb = b - NB1; }
    __shared__ int sh[1024];
    int t = threadIdx.x, i = lb * 1024 + t;
    int v = (i < n) ? in[i] : 0;
    sh[t] = v;
    __syncthreads();
    for (int d = 1; d < 1024; d <<= 1) {
        int add = (t >= d) ? sh[t - d] : 0;
        __syncthreads();
        sh[t] += add;
        __syncthreads();
    }
    if (i < n) outp[i] = sh[t] - v;
    if (t == 1023) part[lb] = sh[1023];
}
__global__ __launch_bounds__(128) void k_scanp_all() {
    int* part = blockIdx.x ? g_part2 : g_part1;
    int nb = blockIdx.x ? NB2 : NB1;
    __shared__ int sh[128];
    int t = threadIdx.x;
    int v = (t < nb) ? part[t] : 0;
    sh[t] = v;
    __syncthreads();
    for (int d = 1; d < 128; d <<= 1) {
        int add = (t >= d) ? sh[t - d] : 0;
        __syncthreads();
        sh[t] += add;
        __syncthreads();
    }
    if (t < nb) part[t] = sh[t] - v;
}
__global__ __launch_bounds__(1024) void k_scana_all() {
    int b = blockIdx.x;
    if (b < NB1) {
        int i = b * 1024 + threadIdx.x;
        if (i < N1v) g_off1[i] += g_part1[b];
    } else {
        int i = (b - NB1) * 1024 + threadIdx.x;
        if (i < N2v) g_off2[i] += g_part2[b - NB1];
    }
}
__global__ void k_scatter_all(const int* __restrict__ dst1, const int* __restrict__ dst2) {
    int i = blockIdx.x * blockDim.x + threadIdx.x;
    if (i < E1v) {
        int d = dst1[i];
        g_eidx1[g_off1[d] + atomicAdd(&g_cur1[d], 1)] = i;
    } else if (i < E1v + E2v) {
        int e = i - E1v;
        int d = dst2[e];
        g_eidx2[g_off2[d] + atomicAdd(&g_cur2[d], 1)] = e;
    }
}
__global__ void k_sort_all() {
    int i = blockIdx.x * blockDim.x + threadIdx.x;
    int a, c; int* eidx;
    if (i < N1v) { a = g_off1[i]; c = g_cnt1[i]; eidx = g_eidx1; }
    else if (i < N1v + N2v) { int j = i - N1v; a = g_off2[j]; c = g_cnt2[j]; eidx = g_eidx2; }
    else return;
    for (int x = 1; x < c; x++) {
        int key = eidx[a + x];
        int y = x - 1;
        while (y >= 0 && eidx[a + y] > key) { eidx[a + y + 1] = eidx[a + y]; y--; }
        eidx[a + y + 1] = key;
    }
}

// ---------------- layer-1 aggregation (fp16 gather, depth-2 prefetch, online softmax) ----------------
__global__ __launch_bounds__(256) void k_agg1(const int* __restrict__ src,
                                              const float* __restrict__ att,
                                              const float* __restrict__ bias) {
    int warp = (blockIdx.x * blockDim.x + threadIdx.x) >> 5;
    int lane = threadIdx.x & 31;
    if (warp >= N1v) return;

    const __half2* xr = reinterpret_cast<const __half2*>(&g_xr1[(size_t)warp * D1v]);
    float2 xrr[4], attr[4];
    float s0[4], s1[4], m[4], d[4];
#pragma unroll
    for (int q = 0; q < 4; q++) {
        int idx = lane + 32 * q;
        xrr[q] = __half22float2(xr[idx]);
        attr[q] = make_float2(att[2 * idx], att[2 * idx + 1]);
        s0[q] = 0.f; s1[q] = 0.f; m[q] = -1e30f; d[q] = 0.f;
    }

    int a0 = g_off1[warp], c = g_cnt1[warp];
    uint32_t xb[4];
    int sn_next = 0;
    if (c > 0) {
        int s0n = src[g_eidx1[a0]];
        const uint32_t* p = reinterpret_cast<const uint32_t*>(&g_xl1[(size_t)s0n * D1v]);
#pragma unroll
        for (int q = 0; q < 4; q++) xb[q] = p[lane + 32 * q];
        if (c > 1) sn_next = src[g_eidx1[a0 + 1]];
    }

    for (int j = 0; j < c; j++) {
        float2 xl[4];
#pragma unroll
        for (int q = 0; q < 4; q++)
            xl[q] = __half22float2(*reinterpret_cast<const __half2*>(&xb[q]));
        if (j + 1 < c) {
            const uint32_t* p = reinterpret_cast<const uint32_t*>(&g_xl1[(size_t)sn_next * D1v]);
#pragma unroll
            for (int q = 0; q < 4; q++) xb[q] = p[lane + 32 * q];
            if (j + 2 < c) sn_next = src[g_eidx1[a0 + j + 2]];
        }
        float p4[4];
#pragma unroll
        for (int q = 0; q < 4; q++) {
            float e0 = xl[q].x + xrr[q].x; e0 = e0 > 0.f ? e0 : 0.2f * e0;
            float e1 = xl[q].y + xrr[q].y; e1 = e1 > 0.f ? e1 : 0.2f * e1;
            p4[q] = e0 * attr[q].x + e1 * attr[q].y;
        }
#pragma unroll
        for (int q = 0; q < 4; q++) p4[q] += __shfl_xor_sync(0xffffffffu, p4[q], 16);
#pragma unroll
        for (int q = 0; q < 4; q++) p4[q] += __shfl_xor_sync(0xffffffffu, p4[q], 8);
        int g = lane >> 3;
        float v = (g == 0) ? p4[0] : (g == 1) ? p4[1] : (g == 2) ? p4[2] : p4[3];
        v += __shfl_xor_sync(0xffffffffu, v, 4);
        v += __shfl_xor_sync(0xffffffffu, v, 2);
        v += __shfl_xor_sync(0xffffffffu, v, 1);
#pragma unroll
        for (int q = 0; q < 4; q++) {
            float hq = __shfl_sync(0xffffffffu, v, q << 3);
            float mn = fmaxf(m[q], hq);
            float c1 = __expf(m[q] - mn);
            float c2 = __expf(hq - mn);
            d[q] = d[q] * c1 + c2;
            m[q] = mn;
            s0[q] = s0[q] * c1 + c2 * xl[q].x;
            s1[q] = s1[q] * c1 + c2 * xl[q].y;
        }
    }
    __nv_bfloat16* hp = &g_h[(size_t)warp * D1v];
#pragma unroll
    for (int q = 0; q < 4; q++) {
        int idx = lane + 32 * q, ch0 = 2 * idx;
        float inv = 1.f / (d[q] + 1e-16f);
        float v0 = s0[q] * inv + bias[ch0];
        float v1 = s1[q] * inv + bias[ch0 + 1];
        v0 = v0 > 0.f ? v0 : 0.f;
        v1 = v1 > 0.f ? v1 : 0.f;
        __nv_bfloat162 hv; hv.x = __float2bfloat16(v0); hv.y = __float2bfloat16(v1);
        *reinterpret_cast<__nv_bfloat162*>(&hp[ch0]) = hv;
    }
}

// ---------------- layer-2 aggregation + bias + log_softmax ----------------
__global__ __launch_bounds__(256) void k_agg2(const int* __restrict__ src,
                                              const float* __restrict__ att,
                                              const float* __restrict__ bias,
                                              float* __restrict__ out) {
    int warp = (blockIdx.x * blockDim.x + threadIdx.x) >> 5;
    int lane = threadIdx.x & 31;
    if (warp >= N2v) return;

    bool ok = lane < 24;
    const __half2* xr = reinterpret_cast<const __half2*>(&g_xr2[(size_t)warp * OUTCv]);
    float2 xrr = ok ? __half22float2(xr[lane]) : make_float2(0.f, 0.f);
    float2 attr = ok ? make_float2(att[2 * lane], att[2 * lane + 1]) : make_float2(0.f, 0.f);
    float s0 = 0.f, s1 = 0.f, m = -1e30f, dd = 0.f;

    int a0 = g_off2[warp], c = g_cnt2[warp];
    uint32_t xb = 0;
    int sn_next = 0;
    if (c > 0) {
        int s0n = src[g_eidx2[a0]];
        if (ok) xb = reinterpret_cast<const uint32_t*>(&g_xl2[(size_t)s0n * OUTCv])[lane];
        if (c > 1) sn_next = src[g_eidx2[a0 + 1]];
    }

    for (int j = 0; j < c; j++) {
        float2 xl = __half22float2(*reinterpret_cast<const __half2*>(&xb));
        if (j + 1 < c) {
            if (ok) xb = reinterpret_cast<const uint32_t*>(&g_xl2[(size_t)sn_next * OUTCv])[lane];
            if (j + 2 < c) sn_next = src[g_eidx2[a0 + j + 2]];
        }
        float e0 = xl.x + xrr.x; e0 = e0 > 0.f ? e0 : 0.2f * e0;
        float e1 = xl.y + xrr.y; e1 = e1 > 0.f ? e1 : 0.2f * e1;
        float p = ok ? (e0 * attr.x + e1 * attr.y) : 0.f;
#pragma unroll
        for (int o = 16; o; o >>= 1) p += __shfl_xor_sync(0xffffffffu, p, o);
        float mn = fmaxf(m, p);
        float c1 = __expf(m - mn);
        float c2 = __expf(p - mn);
        dd = dd * c1 + c2;
        m = mn;
        s0 = s0 * c1 + c2 * xl.x;
        s1 = s1 * c1 + c2 * xl.y;
    }
    float inv = 1.f / (dd + 1e-16f);
    float v0 = ok ? s0 * inv + bias[2 * lane] : -1e30f;
    float v1 = ok ? s1 * inv + bias[2 * lane + 1] : -1e30f;

    float mx = fmaxf(v0, v1);
#pragma unroll
    for (int o = 16; o; o >>= 1) mx = fmaxf(mx, __shfl_xor_sync(0xffffffffu, mx, o));
    float se = ok ? (__expf(v0 - mx) + __expf(v1 - mx)) : 0.f;
#pragma unroll
    for (int o = 16; o; o >>= 1) se += __shfl_xor_sync(0xffffffffu, se, o);
    float lse = mx + logf(se);
    if (ok) {
        float2 r = make_float2(v0 - lse, v1 - lse);
        *reinterpret_cast<float2*>(&out[(size_t)warp * OUTCv + 2 * lane]) = r;
    }
}

// ---------------- launch ----------------
static inline int cdiv(int a, int b) { return (a + b - 1) / b; }

extern "C" void kernel_launch(void* const* d_in, const int* in_sizes, int n_in,
                              void* d_out, int out_size) {
    const float* x     = (const float*)d_in[0];
    const float* Wl1   = (const float*)d_in[1];
    const float* bl1   = (const float*)d_in[2];
    const float* Wr1   = (const float*)d_in[3];
    const float* br1   = (const float*)d_in[4];
    const float* att1  = (const float*)d_in[5];
    const float* bias1 = (const float*)d_in[6];
    const float* Wl2   = (const float*)d_in[7];
    const float* bl2   = (const float*)d_in[8];
    const float* Wr2   = (const float*)d_in[9];
    const float* br2   = (const float*)d_in[10];
    const float* att2  = (const float*)d_in[11];
    const float* bias2 = (const float*)d_in[12];
    const int*   src1  = (const int*)d_in[13];
    const int*   dst1  = (const int*)d_in[14];
    const int*   src2  = (const int*)d_in[15];
    const int*   dst2  = (const int*)d_in[16];
    float* out = (float*)d_out;

    __nv_bfloat16 *xb, *B1l, *B1r, *B2l, *B2r, *hbuf;
    __half *xl1, *xr1, *xl2, *xr2;
    cudaGetSymbolAddress((void**)&xb,    g_xb);
    cudaGetSymbolAddress((void**)&hbuf,  g_h);
    cudaGetSymbolAddress((void**)&B1l,   g_B1l);
    cudaGetSymbolAddress((void**)&B1r,   g_B1r);
    cudaGetSymbolAddress((void**)&B2l,   g_B2l);
    cudaGetSymbolAddress((void**)&B2r,   g_B2r);
    cudaGetSymbolAddress((void**)&xl1,   g_xl1);
    cudaGetSymbolAddress((void**)&xr1,   g_xr1);
    cudaGetSymbolAddress((void**)&xl2,   g_xl2);
    cudaGetSymbolAddress((void**)&xr2,   g_xr2);

    // SMEM: Bs NB*(K+8)*2 + A ring 2*128*40*2
    const int SMEM1 = 256 * (128 + 8) * 2 + 2 * 128 * 40 * 2;   // 90112
    const int SMEM2 = 64  * (256 + 8) * 2 + 2 * 128 * 40 * 2;   // 54272
    cudaFuncSetAttribute(gemm_mma<256, 128>, cudaFuncAttributeMaxDynamicSharedMemorySize, SMEM1);
    cudaFuncSetAttribute(gemm_mma<48, 256>,  cudaFuncAttributeMaxDynamicSharedMemorySize, SMEM2);

    // ---- converts + layer-1 GEMMs first; launch #4 = big GEMM -> ncu ----
    k_cvt<<<cdiv(N0v * INCv / 4, 256), 256>>>(x, xb, N0v * INCv / 4);                         // 1
    k_cvtW_all<<<cdiv(2 * (INCv * D1v + D1v * OUTCv), 256), 256>>>(Wl1, Wr1, Wl2, Wr2);       // 2
    gemm_mma<256, 128><<<148, 512, SMEM1>>>(xb, B1r, br1, xr1, N1v);                          // 3
    gemm_mma<256, 128><<<148, 512, SMEM1>>>(xb, B1l, bl1, xl1, N0v);                          // 4 (profiled)

    // ---- fused CSR build (both layers) ----
    k_zero_all<<<cdiv(N1v, 256), 256>>>();                                                    // 5
    k_count_all<<<cdiv(E1v + E2v, 256), 256>>>(dst1, dst2);                                   // 6
    k_scanb_all<<<NB1 + NB2, 1024>>>();                                                       // 7
    k_scanp_all<<<2, 128>>>();                                                                // 8
    k_scana_all<<<NB1 + NB2, 1024>>>();                                                       // 9
    k_scatter_all<<<cdiv(E1v + E2v, 256), 256>>>(dst1, dst2);                                 // 10
    k_sort_all<<<cdiv(N1v + N2v, 256), 256>>>();                                              // 11

    // ---- layer-1 softmax-aggregate + relu ----
    k_agg1<<<cdiv(N1v * 32, 256), 256>>>(src1, att1, bias1);                                  // 12

    // ---- layer-2 transforms ----
    gemm_mma<48, 256><<<148, 512, SMEM2>>>(hbuf, B2l, bl2, xl2, N1v);                         // 13
    gemm_mma<48, 256><<<125, 512, SMEM2>>>(hbuf, B2r, br2, xr2, N2v);                         // 14

    // ---- layer-2 softmax-aggregate + bias + log_softmax ----
    k_agg2<<<cdiv(N2v * 32, 256), 256>>>(src2, att2, bias2, out);                             // 15

    (void)in_sizes; (void)n_in; (void)out_size;
}

// round 16
// speedup vs baseline: 3.1151x; 1.0940x over previous
#include <cuda_runtime.h>
#include <cuda_bf16.h>
#include <cuda_fp16.h>
#include <cstdint>
#include <cstddef>

// ---------------- problem constants ----------------
#define N0v   320000
#define N1v   80000
#define N2v   16000
#define E1v   800000
#define E2v   160000
#define INCv  128
#define HIDv  64
#define H1c   4
#define OUTCv 48
#define D1v   (H1c*HIDv)   // 256
#define NB1   ((N1v + 1023) / 1024)   // 79
#define NB2   ((N2v + 1023) / 1024)   // 16

// ---------------- scratch (device globals) ----------------
__device__ __nv_bfloat16 g_xb[(size_t)N0v * INCv];        // bf16(x)
__device__ __half g_xl1[(size_t)N0v * D1v];               // fp16 x@Wl1+bl1
__device__ __half g_xr1[(size_t)N1v * D1v];
__device__ __nv_bfloat16 g_h[(size_t)N1v * D1v];          // bf16 relu(h)
__device__ __half g_xl2[(size_t)N1v * OUTCv];
__device__ __half g_xr2[(size_t)N2v * OUTCv];
__device__ __nv_bfloat16 g_B1l[(size_t)D1v * INCv];       // Wl1^T bf16 [256][128]
__device__ __nv_bfloat16 g_B1r[(size_t)D1v * INCv];
__device__ __nv_bfloat16 g_B2l[(size_t)OUTCv * D1v];      // Wl2^T bf16 [48][256]
__device__ __nv_bfloat16 g_B2r[(size_t)OUTCv * D1v];

__device__ int g_cnt1[N1v], g_off1[N1v], g_cur1[N1v];
__device__ int g_cnt2[N2v], g_off2[N2v], g_cur2[N2v];
__device__ int g_eidx1[E1v], g_eidx2[E2v];
__device__ int g_part1[256], g_part2[256];

// ---------------- stream/event resources (created once at module load) ----------------
struct HxRes {
    cudaStream_t s1 = nullptr;
    cudaEvent_t ev[4] = {nullptr, nullptr, nullptr, nullptr};
    HxRes() {
        if (cudaStreamCreateWithFlags(&s1, cudaStreamNonBlocking) != cudaSuccess) { s1 = nullptr; return; }
        for (int i = 0; i < 4; i++) {
            if (cudaEventCreateWithFlags(&ev[i], cudaEventDisableTiming) != cudaSuccess) { s1 = nullptr; return; }
        }
    }
};
static HxRes g_res;

// ---------------- PTX helpers ----------------
__device__ __forceinline__ uint32_t smem_u32(const void* p) {
    uint32_t a;
    asm("{ .reg .u64 t; cvta.to.shared.u64 t, %1; cvt.u32.u64 %0, t; }" : "=r"(a) : "l"(p));
    return a;
}
__device__ __forceinline__ void ldmatrix_x4(uint32_t* r, uint32_t addr) {
    asm volatile("ldmatrix.sync.aligned.m8n8.x4.shared.b16 {%0,%1,%2,%3}, [%4];"
                 : "=r"(r[0]), "=r"(r[1]), "=r"(r[2]), "=r"(r[3]) : "r"(addr));
}
__device__ __forceinline__ void mma_bf16(float* c, const uint32_t* a, uint32_t b0, uint32_t b1) {
    asm volatile("mma.sync.aligned.m16n8k16.row.col.f32.bf16.bf16.f32 "
                 "{%0,%1,%2,%3}, {%4,%5,%6,%7}, {%8,%9}, {%0,%1,%2,%3};"
                 : "+f"(c[0]), "+f"(c[1]), "+f"(c[2]), "+f"(c[3])
                 : "r"(a[0]), "r"(a[1]), "r"(a[2]), "r"(a[3]), "r"(b0), "r"(b1));
}
__device__ __forceinline__ void cp_async16(uint32_t saddr, const void* gptr) {
    asm volatile("cp.async.cg.shared.global [%0], [%1], 16;" :: "r"(saddr), "l"(gptr));
}
#define CP_COMMIT() asm volatile("cp.async.commit_group;" ::: "memory")
#define CP_WAIT(n)  asm volatile("cp.async.wait_group %0;" :: "n"(n) : "memory")

// ---------------- conversions ----------------
__global__ void k_cvt(const float* __restrict__ in, __nv_bfloat16* __restrict__ out, int n4) {
    int i = blockIdx.x * blockDim.x + threadIdx.x;
    if (i >= n4) return;
    float4 v = reinterpret_cast<const float4*>(in)[i];
    __nv_bfloat162 a; a.x = __float2bfloat16(v.x); a.y = __float2bfloat16(v.y);
    __nv_bfloat162 b; b.x = __float2bfloat16(v.z); b.y = __float2bfloat16(v.w);
    uint2 pk;
    pk.x = *reinterpret_cast<uint32_t*>(&a);
    pk.y = *reinterpret_cast<uint32_t*>(&b);
    reinterpret_cast<uint2*>(out)[i] = pk;
}
__global__ void k_cvtW_all(const float* __restrict__ Wl1, const float* __restrict__ Wr1,
                           const float* __restrict__ Wl2, const float* __restrict__ Wr2) {
    const int S1 = INCv * D1v;     // 32768
    const int S2 = D1v * OUTCv;    // 12288
    int i = blockIdx.x * blockDim.x + threadIdx.x;
    const float* W; __nv_bfloat16* out; int N, j;
    if (i < S1)                 { W = Wl1; out = g_B1l; N = D1v;   j = i; }
    else if (i < 2 * S1)        { W = Wr1; out = g_B1r; N = D1v;   j = i - S1; }
    else if (i < 2 * S1 + S2)   { W = Wl2; out = g_B2l; N = OUTCv; j = i - 2 * S1; }
    else if (i < 2 * (S1 + S2)) { W = Wr2; out = g_B2r; N = OUTCv; j = i - 2 * S1 - S2; }
    else return;
    int k = j / N, n = j % N;
    int K = (N == D1v) ? INCv : D1v;
    out[(size_t)n * K + k] = __float2bfloat16(W[j]);
}

// ---------------- HMMA GEMM, tile-pipelined: C[M,N_] = A@B^T + bias, fp16 out ----------------
// Whole 128xK_ A tile double-buffered via one cp.async group per tile; no intra-tile syncs.
template <int N_, int K_>
__global__ __launch_bounds__(512) void gemm_mma(const __nv_bfloat16* __restrict__ A,
                                                const __nv_bfloat16* __restrict__ Bw,
                                                const float* __restrict__ bias,
                                                __half* __restrict__ C, int M) {
    constexpr int NB  = (N_ + 63) & ~63;
    constexpr int LDB = K_ + 8;
    constexpr int LDA = K_ + 8;              // bf16 elems per A smem row (16B-aligned stride)
    constexpr int CH  = K_ / 32;
    constexpr int WN  = NB / 4;
    constexpr int NT  = WN / 8;
    constexpr int NPAIR = NT / 2;
    constexpr int VPR = K_ / 8;              // uint4 vectors per A row
    constexpr int STAGE = 128 * LDA;         // bf16 elems per A stage

    extern __shared__ char smem[];
    __nv_bfloat16* Bs = reinterpret_cast<__nv_bfloat16*>(smem);
    const uint32_t sBs = smem_u32(smem);
    const uint32_t sAs = sBs + NB * LDB * 2;

    const int tid = threadIdx.x, lid = tid & 31, wid = tid >> 5;
    const int wm = wid >> 2, wn = wid & 3;

    // stationary B
    for (int i = tid; i < NB * (K_ / 8); i += 512) {
        int row = i / (K_ / 8), v = (i % (K_ / 8)) * 8;
        uint4 val = make_uint4(0u, 0u, 0u, 0u);
        if (row < N_) val = *reinterpret_cast<const uint4*>(&Bw[(size_t)row * K_ + v]);
        *reinterpret_cast<uint4*>(&Bs[row * LDB + v]) = val;
    }
    __syncthreads();

    const int nTiles = M / 128;

    // prologue: prefetch first tile into stage 0
    {
        const size_t m0 = (size_t)blockIdx.x * 128;
#pragma unroll
        for (int v = 0; v < (128 * VPR) / 512; v++) {
            int idx = tid + v * 512;
            int row = idx / VPR, col = (idx % VPR) * 8;
            cp_async16(sAs + 2 * (row * LDA + col), &A[(m0 + row) * K_ + col]);
        }
        CP_COMMIT();
    }

    int si = 0;
    for (int t = blockIdx.x; t < nTiles; t += gridDim.x) {
        // prefetch next tile into other stage
        if (t + gridDim.x < nTiles) {
            const size_t mn = (size_t)(t + gridDim.x) * 128;
            const int so = (si ^ 1) * STAGE;
#pragma unroll
            for (int v = 0; v < (128 * VPR) / 512; v++) {
                int idx = tid + v * 512;
                int row = idx / VPR, col = (idx % VPR) * 8;
                cp_async16(sAs + 2 * (so + row * LDA + col), &A[(mn + row) * K_ + col]);
            }
            CP_COMMIT();
            CP_WAIT(1);
        } else {
            CP_WAIT(0);
        }
        __syncthreads();

        const size_t m0 = (size_t)t * 128;
        float acc[2][NT][4];
#pragma unroll
        for (int i = 0; i < 2; i++)
#pragma unroll
            for (int j = 0; j < NT; j++)
#pragma unroll
                for (int q = 0; q < 4; q++) acc[i][j][q] = 0.f;

        const int sOff = si * STAGE;
        for (int c = 0; c < CH; c++) {
            const int bk = c * 32;
#pragma unroll
            for (int kt = 0; kt < 2; kt++) {
                uint32_t a[2][4];
#pragma unroll
                for (int mt = 0; mt < 2; mt++) {
                    uint32_t addr = sAs + 2 * (sOff +
                        (wm * 32 + mt * 16 + (lid & 15)) * LDA + bk + kt * 16 + (lid >> 4) * 8);
                    ldmatrix_x4(a[mt], addr);
                }
#pragma unroll
                for (int np = 0; np < NPAIR; np++) {
                    uint32_t b[4];
                    int g = lid >> 3;
                    int nrow = wn * WN + np * 16 + ((g >> 1) << 3) + (lid & 7);
                    int col  = bk + kt * 16 + ((g & 1) << 3);
                    ldmatrix_x4(b, sBs + 2 * (nrow * LDB + col));
                    mma_bf16(acc[0][np * 2 + 0], a[0], b[0], b[1]);
                    mma_bf16(acc[0][np * 2 + 1], a[0], b[2], b[3]);
                    mma_bf16(acc[1][np * 2 + 0], a[1], b[0], b[1]);
                    mma_bf16(acc[1][np * 2 + 1], a[1], b[2], b[3]);
                }
            }
        }

        // epilogue: bias + fp16 store
#pragma unroll
        for (int mt = 0; mt < 2; mt++) {
#pragma unroll
            for (int nt = 0; nt < NT; nt++) {
                int colb = wn * WN + nt * 8 + (lid & 3) * 2;
                if (colb < N_) {
                    size_t r0 = m0 + wm * 32 + mt * 16 + (lid >> 2);
                    float b0 = bias[colb], b1 = bias[colb + 1];
                    __half2 v0 = __floats2half2_rn(acc[mt][nt][0] + b0, acc[mt][nt][1] + b1);
                    __half2 v1 = __floats2half2_rn(acc[mt][nt][2] + b0, acc[mt][nt][3] + b1);
                    *reinterpret_cast<__half2*>(&C[r0 * N_ + colb]) = v0;
                    *reinterpret_cast<__half2*>(&C[(r0 + 8) * N_ + colb]) = v1;
                }
            }
        }
        __syncthreads();   // everyone done with stage si before it is refilled
        si ^= 1;
    }
}

// ---------------- fused CSR build ----------------
__global__ void k_zero_all() {
    int i = blockIdx.x * blockDim.x + threadIdx.x;
    if (i < N1v) { g_cnt1[i] = 0; g_cur1[i] = 0; }
    if (i < N2v) { g_cnt2[i] = 0; g_cur2[i] = 0; }
}
__global__ void k_count_all(const int* __restrict__ dst1, const int* __restrict__ dst2) {
    int i = blockIdx.x * blockDim.x + threadIdx.x;
    if (i < E1v) atomicAdd(&g_cnt1[dst1[i]], 1);
    else if (i < E1v + E2v) atomicAdd(&g_cnt2[dst2[i - E1v]], 1);
}
__global__ __launch_bounds__(1024) void k_scanb_all() {
    int b = blockIdx.x;
    const int* in; int* outp; int* part; int n; int lb;
    if (b < NB1) { in = g_cnt1; outp = g_off1; part = g_part1; n = N1v; lb = b; }
    else         { in = g_cnt2; outp = g_off2; part = g_part2; n = N2v; lb = b - NB1; }
    __shared__ int sh[1024];
    int t = threadIdx.x, i = lb * 1024 + t;
    int v = (i < n) ? in[i] : 0;
    sh[t] = v;
    __syncthreads();
    for (int d = 1; d < 1024; d <<= 1) {
        int add = (t >= d) ? sh[t - d] : 0;
        __syncthreads();
        sh[t] += add;
        __syncthreads();
    }
    if (i < n) outp[i] = sh[t] - v;
    if (t == 1023) part[lb] = sh[1023];
}
__global__ __launch_bounds__(128) void k_scanp_all() {
    int* part = blockIdx.x ? g_part2 : g_part1;
    int nb = blockIdx.x ? NB2 : NB1;
    __shared__ int sh[128];
    int t = threadIdx.x;
    int v = (t < nb) ? part[t] : 0;
    sh[t] = v;
    __syncthreads();
    for (int d = 1; d < 128; d <<= 1) {
        int add = (t >= d) ? sh[t - d] : 0;
        __syncthreads();
        sh[t] += add;
        __syncthreads();
    }
    if (t < nb) part[t] = sh[t] - v;
}
__global__ __launch_bounds__(1024) void k_scana_all() {
    int b = blockIdx.x;
    if (b < NB1) {
        int i = b * 1024 + threadIdx.x;
        if (i < N1v) g_off1[i] += g_part1[b];
    } else {
        int i = (b - NB1) * 1024 + threadIdx.x;
        if (i < N2v) g_off2[i] += g_part2[b - NB1];
    }
}
__global__ void k_scatter_all(const int* __restrict__ dst1, const int* __restrict__ dst2) {
    int i = blockIdx.x * blockDim.x + threadIdx.x;
    if (i < E1v) {
        int d = dst1[i];
        g_eidx1[g_off1[d] + atomicAdd(&g_cur1[d], 1)] = i;
    } else if (i < E1v + E2v) {
        int e = i - E1v;
        int d = dst2[e];
        g_eidx2[g_off2[d] + atomicAdd(&g_cur2[d], 1)] = e;
    }
}
__global__ void k_sort_all() {
    int i = blockIdx.x * blockDim.x + threadIdx.x;
    int a, c; int* eidx;
    if (i < N1v) { a = g_off1[i]; c = g_cnt1[i]; eidx = g_eidx1; }
    else if (i < N1v + N2v) { int j = i - N1v; a = g_off2[j]; c = g_cnt2[j]; eidx = g_eidx2; }
    else return;
    for (int x = 1; x < c; x++) {
        int key = eidx[a + x];
        int y = x - 1;
        while (y >= 0 && eidx[a + y] > key) { eidx[a + y + 1] = eidx[a + y]; y--; }
        eidx[a + y + 1] = key;
    }
}

// ---------------- layer-1 aggregation (fp16 gather, depth-2 prefetch, online softmax) ----------------
__global__ __launch_bounds__(256) void k_agg1(const int* __restrict__ src,
                                              const float* __restrict__ att,
                                              const float* __restrict__ bias) {
    int warp = (blockIdx.x * blockDim.x + threadIdx.x) >> 5;
    int lane = threadIdx.x & 31;
    if (warp >= N1v) return;

    const __half2* xr = reinterpret_cast<const __half2*>(&g_xr1[(size_t)warp * D1v]);
    float2 xrr[4], attr[4];
    float s0[4], s1[4], m[4], d[4];
#pragma unroll
    for (int q = 0; q < 4; q++) {
        int idx = lane + 32 * q;
        xrr[q] = __half22float2(xr[idx]);
        attr[q] = make_float2(att[2 * idx], att[2 * idx + 1]);
        s0[q] = 0.f; s1[q] = 0.f; m[q] = -1e30f; d[q] = 0.f;
    }

    int a0 = g_off1[warp], c = g_cnt1[warp];
    uint32_t xb[4];
    int sn_next = 0;
    if (c > 0) {
        int s0n = src[g_eidx1[a0]];
        const uint32_t* p = reinterpret_cast<const uint32_t*>(&g_xl1[(size_t)s0n * D1v]);
#pragma unroll
        for (int q = 0; q < 4; q++) xb[q] = p[lane + 32 * q];
        if (c > 1) sn_next = src[g_eidx1[a0 + 1]];
    }

    for (int j = 0; j < c; j++) {
        float2 xl[4];
#pragma unroll
        for (int q = 0; q < 4; q++)
            xl[q] = __half22float2(*reinterpret_cast<const __half2*>(&xb[q]));
        if (j + 1 < c) {
            const uint32_t* p = reinterpret_cast<const uint32_t*>(&g_xl1[(size_t)sn_next * D1v]);
#pragma unroll
            for (int q = 0; q < 4; q++) xb[q] = p[lane + 32 * q];
            if (j + 2 < c) sn_next = src[g_eidx1[a0 + j + 2]];
        }
        float p4[4];
#pragma unroll
        for (int q = 0; q < 4; q++) {
            float e0 = xl[q].x + xrr[q].x; e0 = e0 > 0.f ? e0 : 0.2f * e0;
            float e1 = xl[q].y + xrr[q].y; e1 = e1 > 0.f ? e1 : 0.2f * e1;
            p4[q] = e0 * attr[q].x + e1 * attr[q].y;
        }
#pragma unroll
        for (int q = 0; q < 4; q++) p4[q] += __shfl_xor_sync(0xffffffffu, p4[q], 16);
#pragma unroll
        for (int q = 0; q < 4; q++) p4[q] += __shfl_xor_sync(0xffffffffu, p4[q], 8);
        int g = lane >> 3;
        float v = (g == 0) ? p4[0] : (g == 1) ? p4[1] : (g == 2) ? p4[2] : p4[3];
        v += __shfl_xor_sync(0xffffffffu, v, 4);
        v += __shfl_xor_sync(0xffffffffu, v, 2);
        v += __shfl_xor_sync(0xffffffffu, v, 1);
#pragma unroll
        for (int q = 0; q < 4; q++) {
            float hq = __shfl_sync(0xffffffffu, v, q << 3);
            float mn = fmaxf(m[q], hq);
            float c1 = __expf(m[q] - mn);
            float c2 = __expf(hq - mn);
            d[q] = d[q] * c1 + c2;
            m[q] = mn;
            s0[q] = s0[q] * c1 + c2 * xl[q].x;
            s1[q] = s1[q] * c1 + c2 * xl[q].y;
        }
    }
    __nv_bfloat16* hp = &g_h[(size_t)warp * D1v];
#pragma unroll
    for (int q = 0; q < 4; q++) {
        int idx = lane + 32 * q, ch0 = 2 * idx;
        float inv = 1.f / (d[q] + 1e-16f);
        float v0 = s0[q] * inv + bias[ch0];
        float v1 = s1[q] * inv + bias[ch0 + 1];
        v0 = v0 > 0.f ? v0 : 0.f;
        v1 = v1 > 0.f ? v1 : 0.f;
        __nv_bfloat162 hv; hv.x = __float2bfloat16(v0); hv.y = __float2bfloat16(v1);
        *reinterpret_cast<__nv_bfloat162*>(&hp[ch0]) = hv;
    }
}

// ---------------- layer-2 aggregation + bias + log_softmax ----------------
__global__ __launch_bounds__(256) void k_agg2(const int* __restrict__ src,
                                              const float* __restrict__ att,
                                              const float* __restrict__ bias,
                                              float* __restrict__ out) {
    int warp = (blockIdx.x * blockDim.x + threadIdx.x) >> 5;
    int lane = threadIdx.x & 31;
    if (warp >= N2v) return;

    bool ok = lane < 24;
    const __half2* xr = reinterpret_cast<const __half2*>(&g_xr2[(size_t)warp * OUTCv]);
    float2 xrr = ok ? __half22float2(xr[lane]) : make_float2(0.f, 0.f);
    float2 attr = ok ? make_float2(att[2 * lane], att[2 * lane + 1]) : make_float2(0.f, 0.f);
    float s0 = 0.f, s1 = 0.f, m = -1e30f, dd = 0.f;

    int a0 = g_off2[warp], c = g_cnt2[warp];
    uint32_t xb = 0;
    int sn_next = 0;
    if (c > 0) {
        int s0n = src[g_eidx2[a0]];
        if (ok) xb = reinterpret_cast<const uint32_t*>(&g_xl2[(size_t)s0n * OUTCv])[lane];
        if (c > 1) sn_next = src[g_eidx2[a0 + 1]];
    }

    for (int j = 0; j < c; j++) {
        float2 xl = __half22float2(*reinterpret_cast<const __half2*>(&xb));
        if (j + 1 < c) {
            if (ok) xb = reinterpret_cast<const uint32_t*>(&g_xl2[(size_t)sn_next * OUTCv])[lane];
            if (j + 2 < c) sn_next = src[g_eidx2[a0 + j + 2]];
        }
        float e0 = xl.x + xrr.x; e0 = e0 > 0.f ? e0 : 0.2f * e0;
        float e1 = xl.y + xrr.y; e1 = e1 > 0.f ? e1 : 0.2f * e1;
        float p = ok ? (e0 * attr.x + e1 * attr.y) : 0.f;
#pragma unroll
        for (int o = 16; o; o >>= 1) p += __shfl_xor_sync(0xffffffffu, p, o);
        float mn = fmaxf(m, p);
        float c1 = __expf(m - mn);
        float c2 = __expf(p - mn);
        dd = dd * c1 + c2;
        m = mn;
        s0 = s0 * c1 + c2 * xl.x;
        s1 = s1 * c1 + c2 * xl.y;
    }
    float inv = 1.f / (dd + 1e-16f);
    float v0 = ok ? s0 * inv + bias[2 * lane] : -1e30f;
    float v1 = ok ? s1 * inv + bias[2 * lane + 1] : -1e30f;

    float mx = fmaxf(v0, v1);
#pragma unroll
    for (int o = 16; o; o >>= 1) mx = fmaxf(mx, __shfl_xor_sync(0xffffffffu, mx, o));
    float se = ok ? (__expf(v0 - mx) + __expf(v1 - mx)) : 0.f;
#pragma unroll
    for (int o = 16; o; o >>= 1) se += __shfl_xor_sync(0xffffffffu, se, o);
    float lse = mx + logf(se);
    if (ok) {
        float2 r = make_float2(v0 - lse, v1 - lse);
        *reinterpret_cast<float2*>(&out[(size_t)warp * OUTCv + 2 * lane]) = r;
    }
}

// ---------------- launch ----------------
static inline int cdiv(int a, int b) { return (a + b - 1) / b; }

extern "C" void kernel_launch(void* const* d_in, const int* in_sizes, int n_in,
                              void* d_out, int out_size) {
    const float* x     = (const float*)d_in[0];
    const float* Wl1   = (const float*)d_in[1];
    const float* bl1   = (const float*)d_in[2];
    const float* Wr1   = (const float*)d_in[3];
    const float* br1   = (const float*)d_in[4];
    const float* att1  = (const float*)d_in[5];
    const float* bias1 = (const float*)d_in[6];
    const float* Wl2   = (const float*)d_in[7];
    const float* bl2   = (const float*)d_in[8];
    const float* Wr2   = (const float*)d_in[9];
    const float* br2   = (const float*)d_in[10];
    const float* att2  = (const float*)d_in[11];
    const float* bias2 = (const float*)d_in[12];
    const int*   src1  = (const int*)d_in[13];
    const int*   dst1  = (const int*)d_in[14];
    const int*   src2  = (const int*)d_in[15];
    const int*   dst2  = (const int*)d_in[16];
    float* out = (float*)d_out;

    __nv_bfloat16 *xb, *B1l, *B1r, *B2l, *B2r, *hbuf;
    __half *xl1, *xr1, *xl2, *xr2;
    cudaGetSymbolAddress((void**)&xb,    g_xb);
    cudaGetSymbolAddress((void**)&hbuf,  g_h);
    cudaGetSymbolAddress((void**)&B1l,   g_B1l);
    cudaGetSymbolAddress((void**)&B1r,   g_B1r);
    cudaGetSymbolAddress((void**)&B2l,   g_B2l);
    cudaGetSymbolAddress((void**)&B2r,   g_B2r);
    cudaGetSymbolAddress((void**)&xl1,   g_xl1);
    cudaGetSymbolAddress((void**)&xr1,   g_xr1);
    cudaGetSymbolAddress((void**)&xl2,   g_xl2);
    cudaGetSymbolAddress((void**)&xr2,   g_xr2);

    // SMEM: B (NB*(K+8)*2) + A double-buffer (2*128*(K+8)*2)
    const int SMEM1 = 256 * (128 + 8) * 2 + 2 * 128 * (128 + 8) * 2;   // 139264
    const int SMEM2 = 64  * (256 + 8) * 2 + 2 * 128 * (256 + 8) * 2;   // 168960
    cudaFuncSetAttribute(gemm_mma<256, 128>, cudaFuncAttributeMaxDynamicSharedMemorySize, SMEM1);
    cudaFuncSetAttribute(gemm_mma<48, 256>,  cudaFuncAttributeMaxDynamicSharedMemorySize, SMEM2);

    const bool ov = (g_res.s1 != nullptr);
    cudaStream_t cs = ov ? g_res.s1 : (cudaStream_t)0;

    // fork: CSR build runs concurrently with converts + layer-1 GEMMs
    if (ov) {
        cudaEventRecord(g_res.ev[0], 0);
        cudaStreamWaitEvent(g_res.s1, g_res.ev[0], 0);
    }
    // side stream: fused CSR build (both layers)
    k_zero_all<<<cdiv(N1v, 256), 256, 0, cs>>>();
    k_count_all<<<cdiv(E1v + E2v, 256), 256, 0, cs>>>(dst1, dst2);
    k_scanb_all<<<NB1 + NB2, 1024, 0, cs>>>();
    k_scanp_all<<<2, 128, 0, cs>>>();
    k_scana_all<<<NB1 + NB2, 1024, 0, cs>>>();
    k_scatter_all<<<cdiv(E1v + E2v, 256), 256, 0, cs>>>(dst1, dst2);
    k_sort_all<<<cdiv(N1v + N2v, 256), 256, 0, cs>>>();

    // main stream: converts + layer-1 GEMMs
    k_cvt<<<cdiv(N0v * INCv / 4, 256), 256>>>(x, xb, N0v * INCv / 4);
    k_cvtW_all<<<cdiv(2 * (INCv * D1v + D1v * OUTCv), 256), 256>>>(Wl1, Wr1, Wl2, Wr2);
    gemm_mma<256, 128><<<148, 512, SMEM1>>>(xb, B1r, br1, xr1, N1v);
    gemm_mma<256, 128><<<148, 512, SMEM1>>>(xb, B1l, bl1, xl1, N0v);

    // join: agg1 needs CSR + both layer-1 GEMMs
    if (ov) {
        cudaEventRecord(g_res.ev[1], g_res.s1);
        cudaStreamWaitEvent(0, g_res.ev[1], 0);
    }
    k_agg1<<<cdiv(N1v * 32, 256), 256>>>(src1, att1, bias1);

    // layer-2 GEMMs (xr2 co-runs on side stream)
    if (ov) {
        cudaEventRecord(g_res.ev[2], 0);
        cudaStreamWaitEvent(g_res.s1, g_res.ev[2], 0);
    }
    gemm_mma<48, 256><<<125, 512, SMEM2, cs>>>(hbuf, B2r, br2, xr2, N2v);
    gemm_mma<48, 256><<<148, 512, SMEM2>>>(hbuf, B2l, bl2, xl2, N1v);
    if (ov) {
        cudaEventRecord(g_res.ev[3], g_res.s1);
        cudaStreamWaitEvent(0, g_res.ev[3], 0);
    }

    // layer-2 softmax-aggregate + bias + log_softmax
    k_agg2<<<cdiv(N2v * 32, 256), 256>>>(src2, att2, bias2, out);

    (void)in_sizes; (void)n_in; (void)out_size;
}